// round 1
// baseline (speedup 1.0000x reference)
#include <cuda_runtime.h>
#include <stdint.h>

#define DD 128
#define LL 200

// ---------------- device scratch (static globals: allocation-free) ----------
__device__ float g_kW[(size_t)100001 * DD];   // item_emb @ Wk, all items
__device__ float g_klsum[8192];
__device__ float g_nvalid[8192];

// ---------------- threefry2x32 (JAX-compatible) -----------------------------
__device__ __forceinline__ uint32_t rotl32(uint32_t x, int r) {
    return (x << r) | (x >> (32 - r));
}

// Partitionable-mode 32-bit draw: out = x0 ^ x1 of threefry2x32(key, count64)
__device__ __forceinline__ uint32_t threefry32(uint32_t k0, uint32_t k1,
                                               uint32_t x0, uint32_t x1) {
    uint32_t ks2 = k0 ^ k1 ^ 0x1BD11BDAu;
    x0 += k0; x1 += k1;
#define TFR(r) { x0 += x1; x1 = rotl32(x1, r); x1 ^= x0; }
    TFR(13) TFR(15) TFR(26) TFR(6)   x0 += k1;  x1 += ks2 + 1u;
    TFR(17) TFR(29) TFR(16) TFR(24)  x0 += ks2; x1 += k0 + 2u;
    TFR(13) TFR(15) TFR(26) TFR(6)   x0 += k0;  x1 += k1 + 3u;
    TFR(17) TFR(29) TFR(16) TFR(24)  x0 += k1;  x1 += ks2 + 4u;
    TFR(13) TFR(15) TFR(26) TFR(6)   x0 += ks2; x1 += k0 + 5u;
#undef TFR
    return x0 ^ x1;
}

// jax.random.normal float32 path: uniform in [nextafter(-1,0), 1) -> sqrt(2)*erfinv
__device__ __forceinline__ float jax_normal_from_bits(uint32_t bits) {
    float f = __uint_as_float((bits >> 9) | 0x3F800000u) - 1.0f;   // [0,1)
    const float lo = -0.99999994f;                                  // nextafter(-1,0)
    float u = fmaf(f, 1.0f - lo, lo);
    u = fmaxf(lo, u);
    return 1.41421356f * erfinvf(u);
}

// ---------------- block reduction helpers (128 threads) ---------------------
__device__ __forceinline__ float block_sum(float v, float* sRed) {
#pragma unroll
    for (int o = 16; o; o >>= 1) v += __shfl_xor_sync(0xffffffffu, v, o);
    __syncthreads();                       // protect sRed reuse across calls
    if ((threadIdx.x & 31) == 0) sRed[threadIdx.x >> 5] = v;
    __syncthreads();
    return (sRed[0] + sRed[1]) + (sRed[2] + sRed[3]);
}

// ---------------- kernel 1: kW[i] = item_emb[i] @ Wk ------------------------
__global__ __launch_bounds__(128) void kw_kernel(
    const float* __restrict__ item_emb, const float* __restrict__ Wk, int n_rows)
{
    __shared__ float rows[64 * DD];        // 64 item rows, 32 KB
    int tid  = threadIdx.x;
    int base = blockIdx.x * 64;

    const float4* src = reinterpret_cast<const float4*>(item_emb);
    float4* dst = reinterpret_cast<float4*>(rows);
#pragma unroll
    for (int j = 0; j < 16; ++j) {
        int f  = tid + j * 128;            // 0..2047 float4s
        int il = f >> 5, c = f & 31;
        int gi = base + il; if (gi >= n_rows) gi = n_rows - 1;
        dst[f] = src[(size_t)gi * 32 + c];
    }
    __syncthreads();

    int lane = tid & 31, g = tid >> 5;     // g: group of 16 items
    int d0 = lane << 2;
    float4 acc[16];
#pragma unroll
    for (int i = 0; i < 16; ++i) acc[i] = make_float4(0.f, 0.f, 0.f, 0.f);

    const float* rbase = &rows[(g * 16) * DD];
    for (int k = 0; k < DD; ++k) {
        float4 w = __ldg(reinterpret_cast<const float4*>(&Wk[k * DD + d0]));
#pragma unroll
        for (int i = 0; i < 16; ++i) {
            float x = rbase[i * DD + k];
            acc[i].x = fmaf(x, w.x, acc[i].x);
            acc[i].y = fmaf(x, w.y, acc[i].y);
            acc[i].z = fmaf(x, w.z, acc[i].z);
            acc[i].w = fmaf(x, w.w, acc[i].w);
        }
    }
#pragma unroll
    for (int i = 0; i < 16; ++i) {
        int gi = base + g * 16 + i;
        if (gi < n_rows)
            *reinterpret_cast<float4*>(&g_kW[(size_t)gi * DD + d0]) = acc[i];
    }
}

// ---------------- kernel 2: per-batch-row fused BAM + epilogue --------------
__global__ __launch_bounds__(128) void main_kernel(
    const float* __restrict__ user_emb, const float* __restrict__ item_emb,
    const float* __restrict__ Wq,       const float* __restrict__ b_att,
    const float* __restrict__ v_att,
    const float* __restrict__ ln_u_g,   const float* __restrict__ ln_u_b,
    const float* __restrict__ ln_i_g,   const float* __restrict__ ln_i_b,
    const float* __restrict__ pred_W,   const float* __restrict__ pred_b,
    const int*   __restrict__ user_hist,const int*  __restrict__ user_idx,
    const int*   __restrict__ item_idx, float* __restrict__ out, int pad_id)
{
    __shared__ float sQ[DD], sqW[DD];
    __shared__ int   sRef[LL], sMask[LL];
    __shared__ float sS[LL], sW1[LL], sW2[LL];
    __shared__ float sRed[4];

    int b = blockIdx.x, tid = threadIdx.x;
    int u = user_idx[b], t = item_idx[b];

    for (int l = tid; l < LL; l += 128) {
        int r = user_hist[(size_t)u * LL + l];
        sRef[l]  = r;
        sMask[l] = (r != t) && (r != pad_id);
    }
    sQ[tid] = user_emb[(size_t)u * DD + tid];
    __syncthreads();

    // qW = Q @ Wq
    float acc = 0.f;
#pragma unroll 8
    for (int k = 0; k < DD; ++k) acc = fmaf(sQ[k], Wq[k * DD + tid], acc);
    sqW[tid] = acc;
    __syncthreads();

    // ---- scores: warp-per-l, lane owns 4 dims ----
    int lane = tid & 31, warp = tid >> 5;
    int d0 = lane << 2;
    float4 qw4 = *reinterpret_cast<float4*>(&sqW[d0]);
    float4 bb  = __ldg(reinterpret_cast<const float4*>(&b_att[d0]));
    qw4.x += bb.x; qw4.y += bb.y; qw4.z += bb.z; qw4.w += bb.w;
    float4 vv  = __ldg(reinterpret_cast<const float4*>(&v_att[d0]));

    for (int l = warp; l < LL; l += 4) {
        float s = -1e9f;
        if (sMask[l]) {
            float4 kw = *reinterpret_cast<const float4*>(
                &g_kW[(size_t)sRef[l] * DD + d0]);
            float p = tanhf(qw4.x + kw.x) * vv.x;
            p = fmaf(tanhf(qw4.y + kw.y), vv.y, p);
            p = fmaf(tanhf(qw4.z + kw.z), vv.z, p);
            p = fmaf(tanhf(qw4.w + kw.w), vv.w, p);
#pragma unroll
            for (int o = 16; o; o >>= 1) p += __shfl_xor_sync(0xffffffffu, p, o);
            s = p * 0.25f;                 // / TAU
        }
        if (lane == 0) sS[l] = s;
    }
    __syncthreads();

    // ---- masked softmax ----
    float m = -3e38f;
    for (int l = tid; l < LL; l += 128) m = fmaxf(m, sS[l]);
#pragma unroll
    for (int o = 16; o; o >>= 1) m = fmaxf(m, __shfl_xor_sync(0xffffffffu, m, o));
    __syncthreads();
    if (lane == 0) sRed[warp] = m;
    __syncthreads();
    m = fmaxf(fmaxf(sRed[0], sRed[1]), fmaxf(sRed[2], sRed[3]));

    float esum = 0.f, cnt = 0.f;
    for (int l = tid; l < LL; l += 128) {
        float e = expf(sS[l] - m);         // masked slots underflow to 0
        sS[l] = e; esum += e;
        if (sMask[l]) cnt += 1.f;
    }
    esum = block_sum(esum, sRed);
    cnt  = block_sum(cnt,  sRed);
    float nv   = fmaxf(cnt, 1.f);
    float mu_p = -logf(nv);
    float invE = 1.f / esum;

    // ---- sampled weights (two draws, shared alpha) + KL ----
    float klacc = 0.f, ws1 = 0.f, ws2 = 0.f;
    uint32_t b200 = (uint32_t)b * LL;
    for (int l = tid; l < LL; l += 128) {
        float w1 = 0.f, w2 = 0.f;
        if (sMask[l]) {
            float a  = fmaf(sS[l], invE, 1e-24f);   // alpha + 1e-24
            float mu = logf(a);
            float dd = mu - mu_p;
            klacc += 1.8075851f + dd * dd * 0.5f;   // log(10)-0.5+sigq^2/2 + dd^2/2
            uint32_t idx = b200 + (uint32_t)l;
            float e1 = jax_normal_from_bits(threefry32(0u, 1u, 0u, idx));
            float e2 = jax_normal_from_bits(threefry32(0u, 2u, 0u, idx));
            w1 = a * expf(0.1f * e1);
            w2 = a * expf(0.1f * e2);
        }
        sW1[l] = w1; sW2[l] = w2; ws1 += w1; ws2 += w2;
    }
    klacc = block_sum(klacc, sRed);
    ws1   = block_sum(ws1,   sRed);
    ws2   = block_sum(ws2,   sRed);
    if (tid == 0) { g_klsum[b] = klacc; g_nvalid[b] = cnt; }
    float i1 = 1.f / (ws1 + 1e-12f), i2 = 1.f / (ws2 + 1e-12f);
    __syncthreads();

    // ---- ctx accumulation: thread = dim ----
    float a1 = 0.f, a2 = 0.f;
#pragma unroll 4
    for (int l = 0; l < LL; ++l) {
        float v = __ldg(&item_emb[(size_t)sRef[l] * DD + tid]);
        a1 = fmaf(sW1[l], v, a1);
        a2 = fmaf(sW2[l], v, a2);
    }
    a1 *= i1; a2 *= i2;

    // ---- epilogue: 2x layernorm + GMF fuse + prediction head ----
    float pu   = a1 * sQ[tid];
    float mean = block_sum(pu, sRed) * (1.f / DD);
    float dmu  = pu - mean;
    float var  = block_sum(dmu * dmu, sRed) * (1.f / DD);
    float us   = fmaf(dmu * rsqrtf(var + 1e-5f), ln_u_g[tid], ln_u_b[tid]);

    float pi    = a2 * __ldg(&item_emb[(size_t)t * DD + tid]);
    float mean2 = block_sum(pi, sRed) * (1.f / DD);
    float dmi   = pi - mean2;
    float var2  = block_sum(dmi * dmi, sRed) * (1.f / DD);
    float is    = fmaf(dmi * rsqrtf(var2 + 1e-5f), ln_i_g[tid], ln_i_b[tid]);

    float tot = block_sum(us * is * pred_W[tid], sRed);
    if (tid == 0) out[b] = tot + pred_b[0];
}

// ---------------- kernel 3: deterministic KL reduction ----------------------
__global__ __launch_bounds__(256) void finalize_kernel(float* out, int B, int out_idx) {
    __shared__ float sk[8], sn[8];
    int tid = threadIdx.x;
    float k = 0.f, n = 0.f;
    for (int i = tid; i < B; i += 256) { k += g_klsum[i]; n += g_nvalid[i]; }
#pragma unroll
    for (int o = 16; o; o >>= 1) {
        k += __shfl_xor_sync(0xffffffffu, k, o);
        n += __shfl_xor_sync(0xffffffffu, n, o);
    }
    if ((tid & 31) == 0) { sk[tid >> 5] = k; sn[tid >> 5] = n; }
    __syncthreads();
    if (tid == 0) {
        float kt = 0.f, nt = 0.f;
#pragma unroll
        for (int i = 0; i < 8; ++i) { kt += sk[i]; nt += sn[i]; }
        out[out_idx] = 0.25f * kt / fmaxf(nt, 1.f);   // BETA * sum / count
    }
}

// ---------------- launch ----------------------------------------------------
extern "C" void kernel_launch(void* const* d_in, const int* in_sizes, int n_in,
                              void* d_out, int out_size)
{
    const float* user_emb = (const float*)d_in[0];
    const float* item_emb = (const float*)d_in[1];
    const float* Wq       = (const float*)d_in[2];
    const float* Wk       = (const float*)d_in[3];
    const float* b_att    = (const float*)d_in[4];
    const float* v_att    = (const float*)d_in[5];
    const float* ln_u_g   = (const float*)d_in[6];
    const float* ln_u_b   = (const float*)d_in[7];
    const float* ln_i_g   = (const float*)d_in[8];
    const float* ln_i_b   = (const float*)d_in[9];
    const float* pred_W   = (const float*)d_in[10];
    const float* pred_b   = (const float*)d_in[11];
    const int*   user_hist= (const int*)d_in[12];
    const int*   user_idx = (const int*)d_in[13];
    const int*   item_idx = (const int*)d_in[14];

    int B      = in_sizes[13];
    int n_rows = in_sizes[1] / DD;      // 100001 (item table incl. padding row)
    int pad_id = n_rows - 1;            // N_ITEMS

    kw_kernel<<<(n_rows + 63) / 64, 128>>>(item_emb, Wk, n_rows);
    main_kernel<<<B, 128>>>(user_emb, item_emb, Wq, b_att, v_att,
                            ln_u_g, ln_u_b, ln_i_g, ln_i_b, pred_W, pred_b,
                            user_hist, user_idx, item_idx, (float*)d_out, pad_id);
    if (out_size > B)
        finalize_kernel<<<1, 256>>>((float*)d_out, B, out_size - 1);
}

// round 3
// speedup vs baseline: 1.3453x; 1.3453x over previous
#include <cuda_runtime.h>
#include <stdint.h>

#define DD 128
#define LL 200

// ---------------- device scratch (static globals: allocation-free) ----------
__device__ float g_kW[(size_t)100001 * DD];   // item_emb @ Wk, all items
__device__ float g_klsum[8192];
__device__ float g_nvalid[8192];
__device__ int   g_fallback;

__device__ __forceinline__ float cvt_tf32(float x) {
    float r; asm("cvt.rna.tf32.f32 %0, %1;" : "=f"(r) : "f"(x)); return r;
}

// ---------------- kernel 1a: kW via mma.sync tf32 ---------------------------
// Block: 256 threads, tile M=128 (items) x N=128 (out dims) x K=128.
// A smem [m][k] stride 132, B smem transposed [n][k] stride 132.
#define TS 132
#define KW_SMEM_BYTES (2 * 128 * TS * 4)

__global__ __launch_bounds__(256, 1) void kw_mma_kernel(
    const float* __restrict__ item_emb, const float* __restrict__ Wk, int n_rows)
{
    extern __shared__ float smem[];
    float* As = smem;                 // [128][TS]
    float* Bs = smem + 128 * TS;      // [128][TS] (n-major)
    int tid = threadIdx.x, lane = tid & 31, warp = tid >> 5;
    size_t base = (size_t)blockIdx.x * 128;

    // ---- A: coalesced float4 loads, tf32-converted ----
    const float4* A4 = reinterpret_cast<const float4*>(item_emb);
#pragma unroll
    for (int j = 0; j < 16; ++j) {
        int f = tid + j * 256;            // 0..4095
        int m = f >> 5, kc = f & 31;
        size_t gi = base + m; if (gi >= (size_t)n_rows) gi = n_rows - 1;
        float4 v = A4[gi * 32 + kc];
        v.x = cvt_tf32(v.x); v.y = cvt_tf32(v.y);
        v.z = cvt_tf32(v.z); v.w = cvt_tf32(v.w);
        *reinterpret_cast<float4*>(&As[m * TS + kc * 4]) = v;
    }
    // ---- B: coalesced read of Wk[k][n], store transposed [n][k] ----
#pragma unroll
    for (int j = 0; j < 64; ++j) {
        int f = tid + j * 256;            // 0..16383
        int k = f >> 7, n = f & 127;
        Bs[n * TS + k] = cvt_tf32(__ldg(&Wk[k * 128 + n]));
    }
    __syncthreads();

    int gq = lane >> 2, qt = lane & 3;    // group-of-4 id, thread-in-group
    int mrow = warp * 16;

    float c[16][4];
#pragma unroll
    for (int nt = 0; nt < 16; ++nt)
#pragma unroll
        for (int i = 0; i < 4; ++i) c[nt][i] = 0.f;

    const float* Ar0 = &As[(mrow + gq) * TS + qt];
    const float* Ar1 = &As[(mrow + gq + 8) * TS + qt];
    const float* Bq  = &Bs[gq * TS + qt];

#pragma unroll
    for (int ks = 0; ks < 16; ++ks) {
        int k0 = ks * 8;
        uint32_t a0 = __float_as_uint(Ar0[k0]);
        uint32_t a1 = __float_as_uint(Ar1[k0]);
        uint32_t a2 = __float_as_uint(Ar0[k0 + 4]);
        uint32_t a3 = __float_as_uint(Ar1[k0 + 4]);
#pragma unroll
        for (int nt = 0; nt < 16; ++nt) {
            uint32_t b0 = __float_as_uint(Bq[nt * 8 * TS + k0]);
            uint32_t b1 = __float_as_uint(Bq[nt * 8 * TS + k0 + 4]);
            asm volatile(
                "mma.sync.aligned.m16n8k8.row.col.f32.tf32.tf32.f32 "
                "{%0,%1,%2,%3}, {%4,%5,%6,%7}, {%8,%9}, {%0,%1,%2,%3};"
                : "+f"(c[nt][0]), "+f"(c[nt][1]), "+f"(c[nt][2]), "+f"(c[nt][3])
                : "r"(a0), "r"(a1), "r"(a2), "r"(a3), "r"(b0), "r"(b1));
        }
    }

    // ---- store: thread owns (row=mrow+gq, row+8) x cols nt*8+qt*2 (+1) ----
    size_t g0 = base + mrow + gq;
    bool ok0 = g0 < (size_t)n_rows, ok1 = (g0 + 8) < (size_t)n_rows;
#pragma unroll
    for (int nt = 0; nt < 16; ++nt) {
        int col = nt * 8 + qt * 2;
        if (ok0) *reinterpret_cast<float2*>(&g_kW[g0 * 128 + col])
                     = make_float2(c[nt][0], c[nt][1]);
        if (ok1) *reinterpret_cast<float2*>(&g_kW[(g0 + 8) * 128 + col])
                     = make_float2(c[nt][2], c[nt][3]);
    }
}

// ---------------- kernel 1b: spot-check tf32 result vs fp32 -----------------
__global__ __launch_bounds__(128) void kw_check_kernel(
    const float* __restrict__ item_emb, const float* __restrict__ Wk, int n_rows)
{
    int t = threadIdx.x;
    if (t == 0) g_fallback = 0;
    __syncthreads();
    int i = (t * 12347 + 67) % n_rows;
    int e = (t * 37 + 5) & 127;
    float ref = 0.f;
#pragma unroll 8
    for (int d = 0; d < 128; ++d)
        ref = fmaf(item_emb[(size_t)i * 128 + d], Wk[d * 128 + e], ref);
    float got  = g_kW[(size_t)i * 128 + e];
    float diff = fabsf(got - ref);
    if (!(diff <= 0.02f * fabsf(ref) + 1e-4f)) g_fallback = 1;  // catches NaN too
}

// ---------------- kernel 1c: fp32 fallback (runs only if check failed) ------
__global__ __launch_bounds__(128) void kw_fallback_kernel(
    const float* __restrict__ item_emb, const float* __restrict__ Wk, int n_rows)
{
    if (g_fallback == 0) return;
    __shared__ float rows[64 * DD];
    int tid  = threadIdx.x;
    int base = blockIdx.x * 64;

    const float4* src = reinterpret_cast<const float4*>(item_emb);
    float4* dst = reinterpret_cast<float4*>(rows);
#pragma unroll
    for (int j = 0; j < 16; ++j) {
        int f  = tid + j * 128;
        int il = f >> 5, c = f & 31;
        int gi = base + il; if (gi >= n_rows) gi = n_rows - 1;
        dst[f] = src[(size_t)gi * 32 + c];
    }
    __syncthreads();

    int lane = tid & 31, g = tid >> 5;
    int d0 = lane << 2;
    float4 acc[16];
#pragma unroll
    for (int i = 0; i < 16; ++i) acc[i] = make_float4(0.f, 0.f, 0.f, 0.f);

    const float* rbase = &rows[(g * 16) * DD];
    for (int k = 0; k < DD; ++k) {
        float4 w = __ldg(reinterpret_cast<const float4*>(&Wk[k * DD + d0]));
#pragma unroll
        for (int i = 0; i < 16; ++i) {
            float x = rbase[i * DD + k];
            acc[i].x = fmaf(x, w.x, acc[i].x);
            acc[i].y = fmaf(x, w.y, acc[i].y);
            acc[i].z = fmaf(x, w.z, acc[i].z);
            acc[i].w = fmaf(x, w.w, acc[i].w);
        }
    }
#pragma unroll
    for (int i = 0; i < 16; ++i) {
        int gi = base + g * 16 + i;
        if (gi < n_rows)
            *reinterpret_cast<float4*>(&g_kW[(size_t)gi * DD + d0]) = acc[i];
    }
}

// ---------------- threefry2x32 (JAX-compatible) -----------------------------
__device__ __forceinline__ uint32_t rotl32(uint32_t x, int r) {
    return (x << r) | (x >> (32 - r));
}
__device__ __forceinline__ uint32_t threefry32(uint32_t k0, uint32_t k1,
                                               uint32_t x0, uint32_t x1) {
    uint32_t ks2 = k0 ^ k1 ^ 0x1BD11BDAu;
    x0 += k0; x1 += k1;
#define TFR(r) { x0 += x1; x1 = rotl32(x1, r); x1 ^= x0; }
    TFR(13) TFR(15) TFR(26) TFR(6)   x0 += k1;  x1 += ks2 + 1u;
    TFR(17) TFR(29) TFR(16) TFR(24)  x0 += ks2; x1 += k0 + 2u;
    TFR(13) TFR(15) TFR(26) TFR(6)   x0 += k0;  x1 += k1 + 3u;
    TFR(17) TFR(29) TFR(16) TFR(24)  x0 += k1;  x1 += ks2 + 4u;
    TFR(13) TFR(15) TFR(26) TFR(6)   x0 += ks2; x1 += k0 + 5u;
#undef TFR
    return x0 ^ x1;
}
__device__ __forceinline__ float jax_normal_from_bits(uint32_t bits) {
    float f = __uint_as_float((bits >> 9) | 0x3F800000u) - 1.0f;
    const float lo = -0.99999994f;
    float u = fmaf(f, 1.0f - lo, lo);
    u = fmaxf(lo, u);
    return 1.41421356f * erfinvf(u);
}

// ---------------- block reduction helper (128 threads) ----------------------
__device__ __forceinline__ float block_sum(float v, float* sRed) {
#pragma unroll
    for (int o = 16; o; o >>= 1) v += __shfl_xor_sync(0xffffffffu, v, o);
    __syncthreads();
    if ((threadIdx.x & 31) == 0) sRed[threadIdx.x >> 5] = v;
    __syncthreads();
    return (sRed[0] + sRed[1]) + (sRed[2] + sRed[3]);
}

// ---------------- kernel 2: per-batch-row fused BAM + epilogue --------------
__global__ __launch_bounds__(128) void main_kernel(
    const float* __restrict__ user_emb, const float* __restrict__ item_emb,
    const float* __restrict__ Wq,       const float* __restrict__ b_att,
    const float* __restrict__ v_att,
    const float* __restrict__ ln_u_g,   const float* __restrict__ ln_u_b,
    const float* __restrict__ ln_i_g,   const float* __restrict__ ln_i_b,
    const float* __restrict__ pred_W,   const float* __restrict__ pred_b,
    const int*   __restrict__ user_hist,const int*  __restrict__ user_idx,
    const int*   __restrict__ item_idx, float* __restrict__ out, int pad_id)
{
    __shared__ float sQ[DD], sqW[DD];
    __shared__ int   sRef[LL], sMask[LL];
    __shared__ float sS[LL], sW1[LL], sW2[LL];
    __shared__ float sRed[4];

    int b = blockIdx.x, tid = threadIdx.x;
    int u = user_idx[b], t = item_idx[b];

    for (int l = tid; l < LL; l += 128) {
        int r = user_hist[(size_t)u * LL + l];
        sRef[l]  = r;
        sMask[l] = (r != t) && (r != pad_id);
    }
    sQ[tid] = user_emb[(size_t)u * DD + tid];
    __syncthreads();

    float acc = 0.f;
#pragma unroll 8
    for (int k = 0; k < DD; ++k) acc = fmaf(sQ[k], Wq[k * DD + tid], acc);
    sqW[tid] = acc;
    __syncthreads();

    int lane = tid & 31, warp = tid >> 5;
    int d0 = lane << 2;
    float4 qw4 = *reinterpret_cast<float4*>(&sqW[d0]);
    float4 bb  = __ldg(reinterpret_cast<const float4*>(&b_att[d0]));
    qw4.x += bb.x; qw4.y += bb.y; qw4.z += bb.z; qw4.w += bb.w;
    float4 vv  = __ldg(reinterpret_cast<const float4*>(&v_att[d0]));

    for (int l = warp; l < LL; l += 4) {
        float s = -1e9f;
        if (sMask[l]) {
            float4 kw = *reinterpret_cast<const float4*>(
                &g_kW[(size_t)sRef[l] * DD + d0]);
            float p = tanhf(qw4.x + kw.x) * vv.x;
            p = fmaf(tanhf(qw4.y + kw.y), vv.y, p);
            p = fmaf(tanhf(qw4.z + kw.z), vv.z, p);
            p = fmaf(tanhf(qw4.w + kw.w), vv.w, p);
#pragma unroll
            for (int o = 16; o; o >>= 1) p += __shfl_xor_sync(0xffffffffu, p, o);
            s = p * 0.25f;
        }
        if (lane == 0) sS[l] = s;
    }
    __syncthreads();

    float m = -3e38f;
    for (int l = tid; l < LL; l += 128) m = fmaxf(m, sS[l]);
#pragma unroll
    for (int o = 16; o; o >>= 1) m = fmaxf(m, __shfl_xor_sync(0xffffffffu, m, o));
    __syncthreads();
    if (lane == 0) sRed[warp] = m;
    __syncthreads();
    m = fmaxf(fmaxf(sRed[0], sRed[1]), fmaxf(sRed[2], sRed[3]));

    float esum = 0.f, cnt = 0.f;
    for (int l = tid; l < LL; l += 128) {
        float e = expf(sS[l] - m);
        sS[l] = e; esum += e;
        if (sMask[l]) cnt += 1.f;
    }
    esum = block_sum(esum, sRed);
    cnt  = block_sum(cnt,  sRed);
    float nv   = fmaxf(cnt, 1.f);
    float mu_p = -logf(nv);
    float invE = 1.f / esum;

    float klacc = 0.f, ws1 = 0.f, ws2 = 0.f;
    uint32_t b200 = (uint32_t)b * LL;
    for (int l = tid; l < LL; l += 128) {
        float w1 = 0.f, w2 = 0.f;
        if (sMask[l]) {
            float a  = fmaf(sS[l], invE, 1e-24f);
            float mu = logf(a);
            float dd = mu - mu_p;
            klacc += 1.8075851f + dd * dd * 0.5f;
            uint32_t idx = b200 + (uint32_t)l;
            float e1 = jax_normal_from_bits(threefry32(0u, 1u, 0u, idx));
            float e2 = jax_normal_from_bits(threefry32(0u, 2u, 0u, idx));
            w1 = a * expf(0.1f * e1);
            w2 = a * expf(0.1f * e2);
        }
        sW1[l] = w1; sW2[l] = w2; ws1 += w1; ws2 += w2;
    }
    klacc = block_sum(klacc, sRed);
    ws1   = block_sum(ws1,   sRed);
    ws2   = block_sum(ws2,   sRed);
    if (tid == 0) { g_klsum[b] = klacc; g_nvalid[b] = cnt; }
    float i1 = 1.f / (ws1 + 1e-12f), i2 = 1.f / (ws2 + 1e-12f);
    __syncthreads();

    float a1 = 0.f, a2 = 0.f;
#pragma unroll 4
    for (int l = 0; l < LL; ++l) {
        float v = __ldg(&item_emb[(size_t)sRef[l] * DD + tid]);
        a1 = fmaf(sW1[l], v, a1);
        a2 = fmaf(sW2[l], v, a2);
    }
    a1 *= i1; a2 *= i2;

    float pu   = a1 * sQ[tid];
    float mean = block_sum(pu, sRed) * (1.f / DD);
    float dmu  = pu - mean;
    float var  = block_sum(dmu * dmu, sRed) * (1.f / DD);
    float us   = fmaf(dmu * rsqrtf(var + 1e-5f), ln_u_g[tid], ln_u_b[tid]);

    float pi    = a2 * __ldg(&item_emb[(size_t)t * DD + tid]);
    float mean2 = block_sum(pi, sRed) * (1.f / DD);
    float dmi   = pi - mean2;
    float var2  = block_sum(dmi * dmi, sRed) * (1.f / DD);
    float is    = fmaf(dmi * rsqrtf(var2 + 1e-5f), ln_i_g[tid], ln_i_b[tid]);

    float tot = block_sum(us * is * pred_W[tid], sRed);
    if (tid == 0) out[b] = tot + pred_b[0];
}

// ---------------- kernel 3: deterministic KL reduction ----------------------
__global__ __launch_bounds__(256) void finalize_kernel(float* out, int B, int out_idx) {
    __shared__ float sk[8], sn[8];
    int tid = threadIdx.x;
    float k = 0.f, n = 0.f;
    for (int i = tid; i < B; i += 256) { k += g_klsum[i]; n += g_nvalid[i]; }
#pragma unroll
    for (int o = 16; o; o >>= 1) {
        k += __shfl_xor_sync(0xffffffffu, k, o);
        n += __shfl_xor_sync(0xffffffffu, n, o);
    }
    if ((tid & 31) == 0) { sk[tid >> 5] = k; sn[tid >> 5] = n; }
    __syncthreads();
    if (tid == 0) {
        float kt = 0.f, nt = 0.f;
#pragma unroll
        for (int i = 0; i < 8; ++i) { kt += sk[i]; nt += sn[i]; }
        out[out_idx] = 0.25f * kt / fmaxf(nt, 1.f);
    }
}

// ---------------- launch ----------------------------------------------------
extern "C" void kernel_launch(void* const* d_in, const int* in_sizes, int n_in,
                              void* d_out, int out_size)
{
    const float* user_emb = (const float*)d_in[0];
    const float* item_emb = (const float*)d_in[1];
    const float* Wq       = (const float*)d_in[2];
    const float* Wk       = (const float*)d_in[3];
    const float* b_att    = (const float*)d_in[4];
    const float* v_att    = (const float*)d_in[5];
    const float* ln_u_g   = (const float*)d_in[6];
    const float* ln_u_b   = (const float*)d_in[7];
    const float* ln_i_g   = (const float*)d_in[8];
    const float* ln_i_b   = (const float*)d_in[9];
    const float* pred_W   = (const float*)d_in[10];
    const float* pred_b   = (const float*)d_in[11];
    const int*   user_hist= (const int*)d_in[12];
    const int*   user_idx = (const int*)d_in[13];
    const int*   item_idx = (const int*)d_in[14];

    int B      = in_sizes[13];
    int n_rows = in_sizes[1] / DD;      // 100001
    int pad_id = n_rows - 1;

    cudaFuncSetAttribute(kw_mma_kernel,
                         cudaFuncAttributeMaxDynamicSharedMemorySize, KW_SMEM_BYTES);

    kw_mma_kernel<<<(n_rows + 127) / 128, 256, KW_SMEM_BYTES>>>(item_emb, Wk, n_rows);
    kw_check_kernel<<<1, 128>>>(item_emb, Wk, n_rows);
    kw_fallback_kernel<<<(n_rows + 63) / 64, 128>>>(item_emb, Wk, n_rows);
    main_kernel<<<B, 128>>>(user_emb, item_emb, Wq, b_att, v_att,
                            ln_u_g, ln_u_b, ln_i_g, ln_i_b, pred_W, pred_b,
                            user_hist, user_idx, item_idx, (float*)d_out, pad_id);
    if (out_size > B)
        finalize_kernel<<<1, 256>>>((float*)d_out, B, out_size - 1);
}

// round 4
// speedup vs baseline: 1.6442x; 1.2222x over previous
#include <cuda_runtime.h>
#include <stdint.h>

#define DD 128
#define LL 200

// ---------------- device scratch (static globals: allocation-free) ----------
__device__ float g_kW[(size_t)100001 * DD];   // item_emb @ Wk, all items
__device__ float g_qWb[(size_t)8192 * DD];    // user_emb[user_idx] @ Wq + b_att
__device__ float g_klsum[8192];
__device__ float g_nvalid[8192];
__device__ int   g_fallback;

__device__ __forceinline__ float cvt_tf32(float x) {
    float r; asm("cvt.rna.tf32.f32 %0, %1;" : "=f"(r) : "f"(x)); return r;
}
// hybrid tanh: exact-poly for |x|<0.35 (err<4e-5 abs), hw approx otherwise
__device__ __forceinline__ float tanh_fast(float x) {
    float t; asm("tanh.approx.f32 %0, %1;" : "=f"(t) : "f"(x));
    float x2 = x * x;
    float p  = x * fmaf(x2, fmaf(x2, 0.13333333f, -0.33333333f), 1.0f);
    return fabsf(x) < 0.35f ? p : t;
}

// ---------------- mma tile core: C[128x128] = A[128x128] @ B^T --------------
// A rows supplied via gather indices (or identity); B stored [n][k] in smem.
#define TS 132
#define KW_SMEM_BYTES (2 * 128 * TS * 4)

template <bool GATHER>
__device__ __forceinline__ void mma_tile_128(
    const float* __restrict__ Arows, const int* __restrict__ gidx,
    const float* __restrict__ Wmat, const float* __restrict__ bias,
    float* __restrict__ Cout, size_t base, int n_rows, float* smem)
{
    float* As = smem;                 // [128][TS]
    float* Bs = smem + 128 * TS;      // [128][TS] (n-major)
    int tid = threadIdx.x, lane = tid & 31, warp = tid >> 5;

    const float4* A4 = reinterpret_cast<const float4*>(Arows);
#pragma unroll
    for (int j = 0; j < 16; ++j) {
        int f = tid + j * 256;            // 0..4095
        int m = f >> 5, kc = f & 31;
        size_t gi = base + m; if (gi >= (size_t)n_rows) gi = n_rows - 1;
        if (GATHER) gi = (size_t)gidx[gi];
        float4 v = A4[gi * 32 + kc];
        v.x = cvt_tf32(v.x); v.y = cvt_tf32(v.y);
        v.z = cvt_tf32(v.z); v.w = cvt_tf32(v.w);
        *reinterpret_cast<float4*>(&As[m * TS + kc * 4]) = v;
    }
#pragma unroll
    for (int j = 0; j < 64; ++j) {
        int f = tid + j * 256;            // 0..16383
        int k = f >> 7, n = f & 127;
        Bs[n * TS + k] = cvt_tf32(__ldg(&Wmat[k * 128 + n]));
    }
    __syncthreads();

    int gq = lane >> 2, qt = lane & 3;
    int mrow = warp * 16;

    float c[16][4];
#pragma unroll
    for (int nt = 0; nt < 16; ++nt)
#pragma unroll
        for (int i = 0; i < 4; ++i) c[nt][i] = 0.f;

    const float* Ar0 = &As[(mrow + gq) * TS + qt];
    const float* Ar1 = &As[(mrow + gq + 8) * TS + qt];
    const float* Bq  = &Bs[gq * TS + qt];

#pragma unroll
    for (int ks = 0; ks < 16; ++ks) {
        int k0 = ks * 8;
        uint32_t a0 = __float_as_uint(Ar0[k0]);
        uint32_t a1 = __float_as_uint(Ar1[k0]);
        uint32_t a2 = __float_as_uint(Ar0[k0 + 4]);
        uint32_t a3 = __float_as_uint(Ar1[k0 + 4]);
#pragma unroll
        for (int nt = 0; nt < 16; ++nt) {
            uint32_t b0 = __float_as_uint(Bq[nt * 8 * TS + k0]);
            uint32_t b1 = __float_as_uint(Bq[nt * 8 * TS + k0 + 4]);
            asm volatile(
                "mma.sync.aligned.m16n8k8.row.col.f32.tf32.tf32.f32 "
                "{%0,%1,%2,%3}, {%4,%5,%6,%7}, {%8,%9}, {%0,%1,%2,%3};"
                : "+f"(c[nt][0]), "+f"(c[nt][1]), "+f"(c[nt][2]), "+f"(c[nt][3])
                : "r"(a0), "r"(a1), "r"(a2), "r"(a3), "r"(b0), "r"(b1));
        }
    }

    size_t g0 = base + mrow + gq;
    bool ok0 = g0 < (size_t)n_rows, ok1 = (g0 + 8) < (size_t)n_rows;
#pragma unroll
    for (int nt = 0; nt < 16; ++nt) {
        int col = nt * 8 + qt * 2;
        float bx = bias ? __ldg(&bias[col]) : 0.f;
        float by = bias ? __ldg(&bias[col + 1]) : 0.f;
        if (ok0) *reinterpret_cast<float2*>(&Cout[g0 * 128 + col])
                     = make_float2(c[nt][0] + bx, c[nt][1] + by);
        if (ok1) *reinterpret_cast<float2*>(&Cout[(g0 + 8) * 128 + col])
                     = make_float2(c[nt][2] + bx, c[nt][3] + by);
    }
}

__global__ __launch_bounds__(256, 1) void kw_mma_kernel(
    const float* __restrict__ item_emb, const float* __restrict__ Wk, int n_rows)
{
    extern __shared__ float smem[];
    mma_tile_128<false>(item_emb, nullptr, Wk, nullptr, g_kW,
                        (size_t)blockIdx.x * 128, n_rows, smem);
}

__global__ __launch_bounds__(256, 1) void qw_mma_kernel(
    const float* __restrict__ user_emb, const float* __restrict__ Wq,
    const float* __restrict__ b_att, const int* __restrict__ user_idx, int B)
{
    extern __shared__ float smem[];
    mma_tile_128<true>(user_emb, user_idx, Wq, b_att, g_qWb,
                       (size_t)blockIdx.x * 128, B, smem);
}

// ---------------- kw spot-check + fp32 fallback -----------------------------
__global__ __launch_bounds__(128) void kw_check_kernel(
    const float* __restrict__ item_emb, const float* __restrict__ Wk, int n_rows)
{
    int t = threadIdx.x;
    if (t == 0) g_fallback = 0;
    __syncthreads();
    int i = (t * 12347 + 67) % n_rows;
    int e = (t * 37 + 5) & 127;
    float ref = 0.f;
#pragma unroll 8
    for (int d = 0; d < 128; ++d)
        ref = fmaf(item_emb[(size_t)i * 128 + d], Wk[d * 128 + e], ref);
    float got  = g_kW[(size_t)i * 128 + e];
    float diff = fabsf(got - ref);
    if (!(diff <= 0.02f * fabsf(ref) + 1e-4f)) g_fallback = 1;
}

__global__ __launch_bounds__(128) void kw_fallback_kernel(
    const float* __restrict__ item_emb, const float* __restrict__ Wk, int n_rows)
{
    if (g_fallback == 0) return;
    __shared__ float rows[64 * DD];
    int tid  = threadIdx.x;
    int base = blockIdx.x * 64;
    const float4* src = reinterpret_cast<const float4*>(item_emb);
    float4* dst = reinterpret_cast<float4*>(rows);
#pragma unroll
    for (int j = 0; j < 16; ++j) {
        int f  = tid + j * 128;
        int il = f >> 5, c = f & 31;
        int gi = base + il; if (gi >= n_rows) gi = n_rows - 1;
        dst[f] = src[(size_t)gi * 32 + c];
    }
    __syncthreads();
    int lane = tid & 31, g = tid >> 5;
    int d0 = lane << 2;
    float4 acc[16];
#pragma unroll
    for (int i = 0; i < 16; ++i) acc[i] = make_float4(0.f, 0.f, 0.f, 0.f);
    const float* rbase = &rows[(g * 16) * DD];
    for (int k = 0; k < DD; ++k) {
        float4 w = __ldg(reinterpret_cast<const float4*>(&Wk[k * DD + d0]));
#pragma unroll
        for (int i = 0; i < 16; ++i) {
            float x = rbase[i * DD + k];
            acc[i].x = fmaf(x, w.x, acc[i].x);
            acc[i].y = fmaf(x, w.y, acc[i].y);
            acc[i].z = fmaf(x, w.z, acc[i].z);
            acc[i].w = fmaf(x, w.w, acc[i].w);
        }
    }
#pragma unroll
    for (int i = 0; i < 16; ++i) {
        int gi = base + g * 16 + i;
        if (gi < n_rows)
            *reinterpret_cast<float4*>(&g_kW[(size_t)gi * DD + d0]) = acc[i];
    }
}

// ---------------- threefry2x32 (JAX-compatible) -----------------------------
__device__ __forceinline__ uint32_t rotl32(uint32_t x, int r) {
    return (x << r) | (x >> (32 - r));
}
__device__ __forceinline__ uint32_t threefry32(uint32_t k0, uint32_t k1,
                                               uint32_t x0, uint32_t x1) {
    uint32_t ks2 = k0 ^ k1 ^ 0x1BD11BDAu;
    x0 += k0; x1 += k1;
#define TFR(r) { x0 += x1; x1 = rotl32(x1, r); x1 ^= x0; }
    TFR(13) TFR(15) TFR(26) TFR(6)   x0 += k1;  x1 += ks2 + 1u;
    TFR(17) TFR(29) TFR(16) TFR(24)  x0 += ks2; x1 += k0 + 2u;
    TFR(13) TFR(15) TFR(26) TFR(6)   x0 += k0;  x1 += k1 + 3u;
    TFR(17) TFR(29) TFR(16) TFR(24)  x0 += k1;  x1 += ks2 + 4u;
    TFR(13) TFR(15) TFR(26) TFR(6)   x0 += ks2; x1 += k0 + 5u;
#undef TFR
    return x0 ^ x1;
}
__device__ __forceinline__ float jax_normal_from_bits(uint32_t bits) {
    float f = __uint_as_float((bits >> 9) | 0x3F800000u) - 1.0f;
    const float lo = -0.99999994f;
    float u = fmaf(f, 1.0f - lo, lo);
    u = fmaxf(lo, u);
    return 1.41421356f * erfinvf(u);
}

// ---------------- block reduction helper (128 threads) ----------------------
__device__ __forceinline__ float block_sum(float v, float* sRed) {
#pragma unroll
    for (int o = 16; o; o >>= 1) v += __shfl_xor_sync(0xffffffffu, v, o);
    __syncthreads();
    if ((threadIdx.x & 31) == 0) sRed[threadIdx.x >> 5] = v;
    __syncthreads();
    return (sRed[0] + sRed[1]) + (sRed[2] + sRed[3]);
}

// ---------------- kernel 2: per-batch-row fused BAM + epilogue --------------
__global__ __launch_bounds__(128) void main_kernel(
    const float* __restrict__ user_emb, const float* __restrict__ item_emb,
    const float* __restrict__ v_att,
    const float* __restrict__ ln_u_g,   const float* __restrict__ ln_u_b,
    const float* __restrict__ ln_i_g,   const float* __restrict__ ln_i_b,
    const float* __restrict__ pred_W,   const float* __restrict__ pred_b,
    const int*   __restrict__ user_hist,const int*  __restrict__ user_idx,
    const int*   __restrict__ item_idx, float* __restrict__ out, int pad_id)
{
    __shared__ float sQ[DD];
    __shared__ int   sRef[LL], sMask[LL];
    __shared__ float sS[LL], sW1[LL], sW2[LL];
    __shared__ float sRed[4];

    int b = blockIdx.x, tid = threadIdx.x;
    int u = user_idx[b], t = item_idx[b];

    for (int l = tid; l < LL; l += 128) {
        int r = user_hist[(size_t)u * LL + l];
        sRef[l]  = r;
        sMask[l] = (r != t) && (r != pad_id);
    }
    sQ[tid] = user_emb[(size_t)u * DD + tid];
    __syncthreads();

    int lane = tid & 31, warp = tid >> 5;
    int d0 = lane << 2;
    // precomputed qWb row (Q@Wq + b_att)
    float4 qw4 = *reinterpret_cast<const float4*>(&g_qWb[(size_t)b * DD + d0]);
    float4 vv  = __ldg(reinterpret_cast<const float4*>(&v_att[d0]));

#pragma unroll 2
    for (int l = warp; l < LL; l += 4) {
        float s = -1e9f;
        if (sMask[l]) {
            float4 kw = *reinterpret_cast<const float4*>(
                &g_kW[(size_t)sRef[l] * DD + d0]);
            float p = tanh_fast(qw4.x + kw.x) * vv.x;
            p = fmaf(tanh_fast(qw4.y + kw.y), vv.y, p);
            p = fmaf(tanh_fast(qw4.z + kw.z), vv.z, p);
            p = fmaf(tanh_fast(qw4.w + kw.w), vv.w, p);
#pragma unroll
            for (int o = 16; o; o >>= 1) p += __shfl_xor_sync(0xffffffffu, p, o);
            s = p * 0.25f;
        }
        if (lane == 0) sS[l] = s;
    }
    __syncthreads();

    float m = -3e38f;
    for (int l = tid; l < LL; l += 128) m = fmaxf(m, sS[l]);
#pragma unroll
    for (int o = 16; o; o >>= 1) m = fmaxf(m, __shfl_xor_sync(0xffffffffu, m, o));
    __syncthreads();
    if (lane == 0) sRed[warp] = m;
    __syncthreads();
    m = fmaxf(fmaxf(sRed[0], sRed[1]), fmaxf(sRed[2], sRed[3]));

    float esum = 0.f, cnt = 0.f;
    for (int l = tid; l < LL; l += 128) {
        float e = __expf(sS[l] - m);
        sS[l] = e; esum += e;
        if (sMask[l]) cnt += 1.f;
    }
    esum = block_sum(esum, sRed);
    cnt  = block_sum(cnt,  sRed);
    float nv   = fmaxf(cnt, 1.f);
    float mu_p = -__logf(nv);
    float invE = 1.f / esum;

    float klacc = 0.f, ws1 = 0.f, ws2 = 0.f;
    uint32_t b200 = (uint32_t)b * LL;
    for (int l = tid; l < LL; l += 128) {
        float w1 = 0.f, w2 = 0.f;
        if (sMask[l]) {
            float a  = fmaf(sS[l], invE, 1e-24f);
            float mu = __logf(a);
            float dd = mu - mu_p;
            klacc += 1.8075851f + dd * dd * 0.5f;
            uint32_t idx = b200 + (uint32_t)l;
            float e1 = jax_normal_from_bits(threefry32(0u, 1u, 0u, idx));
            float e2 = jax_normal_from_bits(threefry32(0u, 2u, 0u, idx));
            w1 = a * __expf(0.1f * e1);
            w2 = a * __expf(0.1f * e2);
        }
        sW1[l] = w1; sW2[l] = w2; ws1 += w1; ws2 += w2;
    }
    klacc = block_sum(klacc, sRed);
    ws1   = block_sum(ws1,   sRed);
    ws2   = block_sum(ws2,   sRed);
    if (tid == 0) { g_klsum[b] = klacc; g_nvalid[b] = cnt; }
    float i1 = 1.f / (ws1 + 1e-12f), i2 = 1.f / (ws2 + 1e-12f);
    __syncthreads();

    // ---- ctx accumulation: thread = dim, vectorized weight loads ----
    float a1 = 0.f, a2 = 0.f;
    const float* ie = item_emb + tid;
#pragma unroll 2
    for (int l4 = 0; l4 < LL / 4; ++l4) {
        float4 w1 = *reinterpret_cast<const float4*>(&sW1[l4 * 4]);
        float4 w2 = *reinterpret_cast<const float4*>(&sW2[l4 * 4]);
        int4   rr = *reinterpret_cast<const int4*>(&sRef[l4 * 4]);
        float v0 = __ldg(ie + (size_t)rr.x * DD);
        float v1 = __ldg(ie + (size_t)rr.y * DD);
        float v2 = __ldg(ie + (size_t)rr.z * DD);
        float v3 = __ldg(ie + (size_t)rr.w * DD);
        a1 = fmaf(w1.x, v0, a1); a2 = fmaf(w2.x, v0, a2);
        a1 = fmaf(w1.y, v1, a1); a2 = fmaf(w2.y, v1, a2);
        a1 = fmaf(w1.z, v2, a1); a2 = fmaf(w2.z, v2, a2);
        a1 = fmaf(w1.w, v3, a1); a2 = fmaf(w2.w, v3, a2);
    }
    a1 *= i1; a2 *= i2;

    float pu   = a1 * sQ[tid];
    float mean = block_sum(pu, sRed) * (1.f / DD);
    float dmu  = pu - mean;
    float var  = block_sum(dmu * dmu, sRed) * (1.f / DD);
    float us   = fmaf(dmu * rsqrtf(var + 1e-5f), ln_u_g[tid], ln_u_b[tid]);

    float pi    = a2 * __ldg(&item_emb[(size_t)t * DD + tid]);
    float mean2 = block_sum(pi, sRed) * (1.f / DD);
    float dmi   = pi - mean2;
    float var2  = block_sum(dmi * dmi, sRed) * (1.f / DD);
    float is    = fmaf(dmi * rsqrtf(var2 + 1e-5f), ln_i_g[tid], ln_i_b[tid]);

    float tot = block_sum(us * is * pred_W[tid], sRed);
    if (tid == 0) out[b] = tot + pred_b[0];
}

// ---------------- kernel 3: deterministic KL reduction ----------------------
__global__ __launch_bounds__(256) void finalize_kernel(float* out, int B, int out_idx) {
    __shared__ float sk[8], sn[8];
    int tid = threadIdx.x;
    float k = 0.f, n = 0.f;
    for (int i = tid; i < B; i += 256) { k += g_klsum[i]; n += g_nvalid[i]; }
#pragma unroll
    for (int o = 16; o; o >>= 1) {
        k += __shfl_xor_sync(0xffffffffu, k, o);
        n += __shfl_xor_sync(0xffffffffu, n, o);
    }
    if ((tid & 31) == 0) { sk[tid >> 5] = k; sn[tid >> 5] = n; }
    __syncthreads();
    if (tid == 0) {
        float kt = 0.f, nt = 0.f;
#pragma unroll
        for (int i = 0; i < 8; ++i) { kt += sk[i]; nt += sn[i]; }
        out[out_idx] = 0.25f * kt / fmaxf(nt, 1.f);
    }
}

// ---------------- launch ----------------------------------------------------
extern "C" void kernel_launch(void* const* d_in, const int* in_sizes, int n_in,
                              void* d_out, int out_size)
{
    const float* user_emb = (const float*)d_in[0];
    const float* item_emb = (const float*)d_in[1];
    const float* Wq       = (const float*)d_in[2];
    const float* Wk       = (const float*)d_in[3];
    const float* b_att    = (const float*)d_in[4];
    const float* v_att    = (const float*)d_in[5];
    const float* ln_u_g   = (const float*)d_in[6];
    const float* ln_u_b   = (const float*)d_in[7];
    const float* ln_i_g   = (const float*)d_in[8];
    const float* ln_i_b   = (const float*)d_in[9];
    const float* pred_W   = (const float*)d_in[10];
    const float* pred_b   = (const float*)d_in[11];
    const int*   user_hist= (const int*)d_in[12];
    const int*   user_idx = (const int*)d_in[13];
    const int*   item_idx = (const int*)d_in[14];

    int B      = in_sizes[13];
    int n_rows = in_sizes[1] / DD;      // 100001
    int pad_id = n_rows - 1;

    cudaFuncSetAttribute(kw_mma_kernel,
                         cudaFuncAttributeMaxDynamicSharedMemorySize, KW_SMEM_BYTES);
    cudaFuncSetAttribute(qw_mma_kernel,
                         cudaFuncAttributeMaxDynamicSharedMemorySize, KW_SMEM_BYTES);

    kw_mma_kernel<<<(n_rows + 127) / 128, 256, KW_SMEM_BYTES>>>(item_emb, Wk, n_rows);
    qw_mma_kernel<<<(B + 127) / 128, 256, KW_SMEM_BYTES>>>(user_emb, Wq, b_att,
                                                            user_idx, B);
    kw_check_kernel<<<1, 128>>>(item_emb, Wk, n_rows);
    kw_fallback_kernel<<<(n_rows + 63) / 64, 128>>>(item_emb, Wk, n_rows);
    main_kernel<<<B, 128>>>(user_emb, item_emb, v_att,
                            ln_u_g, ln_u_b, ln_i_g, ln_i_b, pred_W, pred_b,
                            user_hist, user_idx, item_idx, (float*)d_out, pad_id);
    if (out_size > B)
        finalize_kernel<<<1, 256>>>((float*)d_out, B, out_size - 1);
}

// round 5
// speedup vs baseline: 1.8146x; 1.1036x over previous
#include <cuda_runtime.h>
#include <stdint.h>

#define DD 128
#define LL 200

// ---------------- device scratch (static globals: allocation-free) ----------
__device__ float g_kW[(size_t)100001 * DD];   // item_emb @ Wk, all items
__device__ float g_qWb[(size_t)8192 * DD];    // user_emb[user_idx] @ Wq + b_att
__device__ float g_klsum[8192];
__device__ float g_nvalid[8192];

__device__ __forceinline__ float cvt_tf32(float x) {
    float r; asm("cvt.rna.tf32.f32 %0, %1;" : "=f"(r) : "f"(x)); return r;
}
__device__ __forceinline__ float tanh_hw(float x) {
    float t; asm("tanh.approx.f32 %0, %1;" : "=f"(t) : "f"(x)); return t;
}

// ---------------- mma tile core: C[64x128] = A[64x128] @ B^T ----------------
// Warp tile M=16 x N=64, warps arranged 4m x 2n. 2 blocks/SM.
#define TS 132
#define MB 64
#define KW_SMEM_BYTES ((MB + 128) * TS * 4)

template <bool GATHER>
__device__ __forceinline__ void mma_tile(
    const float* __restrict__ Arows, const int* __restrict__ gidx,
    const float* __restrict__ Wmat, const float* __restrict__ bias,
    float* __restrict__ Cout, size_t base, int n_rows, float* smem)
{
    float* As = smem;                 // [MB][TS]
    float* Bs = smem + MB * TS;       // [128][TS] (n-major)
    int tid = threadIdx.x, lane = tid & 31, warp = tid >> 5;

    const float4* A4 = reinterpret_cast<const float4*>(Arows);
#pragma unroll
    for (int j = 0; j < 8; ++j) {
        int f = tid + j * 256;            // 0..2047 float4s
        int m = f >> 5, kc = f & 31;
        size_t gi = base + m; if (gi >= (size_t)n_rows) gi = n_rows - 1;
        if (GATHER) gi = (size_t)gidx[gi];
        float4 v = A4[gi * 32 + kc];
        v.x = cvt_tf32(v.x); v.y = cvt_tf32(v.y);
        v.z = cvt_tf32(v.z); v.w = cvt_tf32(v.w);
        *reinterpret_cast<float4*>(&As[m * TS + kc * 4]) = v;
    }
#pragma unroll
    for (int j = 0; j < 64; ++j) {
        int f = tid + j * 256;            // 0..16383
        int k = f >> 7, n = f & 127;
        Bs[n * TS + k] = cvt_tf32(__ldg(&Wmat[k * 128 + n]));
    }
    __syncthreads();

    int gq = lane >> 2, qt = lane & 3;
    int mrow = (warp >> 1) * 16;
    int ncol = (warp & 1) * 64;

    float c[8][4];
#pragma unroll
    for (int nt = 0; nt < 8; ++nt)
#pragma unroll
        for (int i = 0; i < 4; ++i) c[nt][i] = 0.f;

    const float* Ar0 = &As[(mrow + gq) * TS + qt];
    const float* Ar1 = Ar0 + 8 * TS;
    const float* Bq  = &Bs[(ncol + gq) * TS + qt];

#pragma unroll
    for (int ks = 0; ks < 16; ++ks) {
        int k0 = ks * 8;
        uint32_t a0 = __float_as_uint(Ar0[k0]);
        uint32_t a1 = __float_as_uint(Ar1[k0]);
        uint32_t a2 = __float_as_uint(Ar0[k0 + 4]);
        uint32_t a3 = __float_as_uint(Ar1[k0 + 4]);
#pragma unroll
        for (int nt = 0; nt < 8; ++nt) {
            uint32_t b0 = __float_as_uint(Bq[nt * 8 * TS + k0]);
            uint32_t b1 = __float_as_uint(Bq[nt * 8 * TS + k0 + 4]);
            asm volatile(
                "mma.sync.aligned.m16n8k8.row.col.f32.tf32.tf32.f32 "
                "{%0,%1,%2,%3}, {%4,%5,%6,%7}, {%8,%9}, {%0,%1,%2,%3};"
                : "+f"(c[nt][0]), "+f"(c[nt][1]), "+f"(c[nt][2]), "+f"(c[nt][3])
                : "r"(a0), "r"(a1), "r"(a2), "r"(a3), "r"(b0), "r"(b1));
        }
    }

    size_t g0 = base + mrow + gq;
    bool ok0 = g0 < (size_t)n_rows, ok1 = (g0 + 8) < (size_t)n_rows;
#pragma unroll
    for (int nt = 0; nt < 8; ++nt) {
        int col = ncol + nt * 8 + qt * 2;
        float bx = bias ? __ldg(&bias[col]) : 0.f;
        float by = bias ? __ldg(&bias[col + 1]) : 0.f;
        if (ok0) *reinterpret_cast<float2*>(&Cout[g0 * 128 + col])
                     = make_float2(c[nt][0] + bx, c[nt][1] + by);
        if (ok1) *reinterpret_cast<float2*>(&Cout[(g0 + 8) * 128 + col])
                     = make_float2(c[nt][2] + bx, c[nt][3] + by);
    }
}

__global__ __launch_bounds__(256, 2) void kw_mma_kernel(
    const float* __restrict__ item_emb, const float* __restrict__ Wk, int n_rows)
{
    extern __shared__ float smem[];
    mma_tile<false>(item_emb, nullptr, Wk, nullptr, g_kW,
                    (size_t)blockIdx.x * MB, n_rows, smem);
}

__global__ __launch_bounds__(256, 2) void qw_mma_kernel(
    const float* __restrict__ user_emb, const float* __restrict__ Wq,
    const float* __restrict__ b_att, const int* __restrict__ user_idx, int B)
{
    extern __shared__ float smem[];
    mma_tile<true>(user_emb, user_idx, Wq, b_att, g_qWb,
                   (size_t)blockIdx.x * MB, B, smem);
}

// ---------------- threefry2x32 (JAX-compatible) -----------------------------
__device__ __forceinline__ uint32_t rotl32(uint32_t x, int r) {
    return (x << r) | (x >> (32 - r));
}
__device__ __forceinline__ uint32_t threefry32(uint32_t k0, uint32_t k1,
                                               uint32_t x0, uint32_t x1) {
    uint32_t ks2 = k0 ^ k1 ^ 0x1BD11BDAu;
    x0 += k0; x1 += k1;
#define TFR(r) { x0 += x1; x1 = rotl32(x1, r); x1 ^= x0; }
    TFR(13) TFR(15) TFR(26) TFR(6)   x0 += k1;  x1 += ks2 + 1u;
    TFR(17) TFR(29) TFR(16) TFR(24)  x0 += ks2; x1 += k0 + 2u;
    TFR(13) TFR(15) TFR(26) TFR(6)   x0 += k0;  x1 += k1 + 3u;
    TFR(17) TFR(29) TFR(16) TFR(24)  x0 += k1;  x1 += ks2 + 4u;
    TFR(13) TFR(15) TFR(26) TFR(6)   x0 += ks2; x1 += k0 + 5u;
#undef TFR
    return x0 ^ x1;
}
__device__ __forceinline__ float jax_normal_from_bits(uint32_t bits) {
    float f = __uint_as_float((bits >> 9) | 0x3F800000u) - 1.0f;
    const float lo = -0.99999994f;
    float u = fmaf(f, 1.0f - lo, lo);
    u = fmaxf(lo, u);
    return 1.41421356f * erfinvf(u);
}

// ---------------- block reduction helper (128 threads) ----------------------
__device__ __forceinline__ float block_sum(float v, float* sRed) {
#pragma unroll
    for (int o = 16; o; o >>= 1) v += __shfl_xor_sync(0xffffffffu, v, o);
    __syncthreads();
    if ((threadIdx.x & 31) == 0) sRed[threadIdx.x >> 5] = v;
    __syncthreads();
    return (sRed[0] + sRed[1]) + (sRed[2] + sRed[3]);
}

// ---------------- kernel 2: per-batch-row fused BAM + epilogue --------------
__global__ __launch_bounds__(128) void main_kernel(
    const float* __restrict__ user_emb, const float* __restrict__ item_emb,
    const float* __restrict__ v_att,
    const float* __restrict__ ln_u_g,   const float* __restrict__ ln_u_b,
    const float* __restrict__ ln_i_g,   const float* __restrict__ ln_i_b,
    const float* __restrict__ pred_W,   const float* __restrict__ pred_b,
    const int*   __restrict__ user_hist,const int*  __restrict__ user_idx,
    const int*   __restrict__ item_idx, float* __restrict__ out, int pad_id)
{
    __shared__ float sQ[DD];
    __shared__ int   sRef[LL], sMask[LL];
    __shared__ float sS[LL], sW1[LL], sW2[LL];
    __shared__ float sRed[4];

    int b = blockIdx.x, tid = threadIdx.x;
    int u = user_idx[b], t = item_idx[b];

    for (int l = tid; l < LL; l += 128) {
        int r = user_hist[(size_t)u * LL + l];
        sRef[l]  = r;
        sMask[l] = (r != t) && (r != pad_id);
    }
    sQ[tid] = user_emb[(size_t)u * DD + tid];
    __syncthreads();

    int lane = tid & 31, warp = tid >> 5;

    // ---- scores: warp handles 2 l per iter; 16 lanes x 8 dims each ----
    {
        int half = lane >> 4, hl = lane & 15;
        int d0 = hl * 8;
        const float* qp = &g_qWb[(size_t)b * DD + d0];
        float4 qa = *reinterpret_cast<const float4*>(qp);
        float4 qb = *reinterpret_cast<const float4*>(qp + 4);
        float4 va = __ldg(reinterpret_cast<const float4*>(&v_att[d0]));
        float4 vb = __ldg(reinterpret_cast<const float4*>(&v_att[d0 + 4]));
        int lbase = warp * 2 + half;
#pragma unroll 2
        for (int i = 0; i < 25; ++i) {
            int l = lbase + i * 8;
            bool mk = sMask[l] != 0;
            float p = 0.f;
            if (mk) {
                const float* kp = &g_kW[(size_t)sRef[l] * DD + d0];
                float4 ka = *reinterpret_cast<const float4*>(kp);
                float4 kb = *reinterpret_cast<const float4*>(kp + 4);
                p =            tanh_hw(qa.x + ka.x) * va.x;
                p = fmaf(tanh_hw(qa.y + ka.y), va.y, p);
                p = fmaf(tanh_hw(qa.z + ka.z), va.z, p);
                p = fmaf(tanh_hw(qa.w + ka.w), va.w, p);
                p = fmaf(tanh_hw(qb.x + kb.x), vb.x, p);
                p = fmaf(tanh_hw(qb.y + kb.y), vb.y, p);
                p = fmaf(tanh_hw(qb.z + kb.z), vb.z, p);
                p = fmaf(tanh_hw(qb.w + kb.w), vb.w, p);
            }
#pragma unroll
            for (int o = 8; o; o >>= 1) p += __shfl_xor_sync(0xffffffffu, p, o);
            if (hl == 0) sS[l] = mk ? p * 0.25f : -1e9f;
        }
    }
    __syncthreads();

    // ---- masked softmax ----
    float m = -3e38f;
    for (int l = tid; l < LL; l += 128) m = fmaxf(m, sS[l]);
#pragma unroll
    for (int o = 16; o; o >>= 1) m = fmaxf(m, __shfl_xor_sync(0xffffffffu, m, o));
    __syncthreads();
    if (lane == 0) sRed[warp] = m;
    __syncthreads();
    m = fmaxf(fmaxf(sRed[0], sRed[1]), fmaxf(sRed[2], sRed[3]));

    float esum = 0.f, cnt = 0.f;
    for (int l = tid; l < LL; l += 128) {
        float e = __expf(sS[l] - m);
        sS[l] = e; esum += e;
        if (sMask[l]) cnt += 1.f;
    }
    esum = block_sum(esum, sRed);
    cnt  = block_sum(cnt,  sRed);
    float nv   = fmaxf(cnt, 1.f);
    float mu_p = -__logf(nv);
    float invE = 1.f / esum;

    // ---- sampled weights (two draws, shared alpha) + KL ----
    float klacc = 0.f, ws1 = 0.f, ws2 = 0.f;
    uint32_t b200 = (uint32_t)b * LL;
    for (int l = tid; l < LL; l += 128) {
        float w1 = 0.f, w2 = 0.f;
        if (sMask[l]) {
            float a  = fmaf(sS[l], invE, 1e-24f);
            float mu = __logf(a);
            float dd = mu - mu_p;
            klacc += 1.8075851f + dd * dd * 0.5f;
            uint32_t idx = b200 + (uint32_t)l;
            float e1 = jax_normal_from_bits(threefry32(0u, 1u, 0u, idx));
            float e2 = jax_normal_from_bits(threefry32(0u, 2u, 0u, idx));
            w1 = a * __expf(0.1f * e1);
            w2 = a * __expf(0.1f * e2);
        }
        sW1[l] = w1; sW2[l] = w2; ws1 += w1; ws2 += w2;
    }
    klacc = block_sum(klacc, sRed);
    ws1   = block_sum(ws1,   sRed);
    ws2   = block_sum(ws2,   sRed);
    if (tid == 0) { g_klsum[b] = klacc; g_nvalid[b] = cnt; }
    float i1 = 1.f / (ws1 + 1e-12f), i2 = 1.f / (ws2 + 1e-12f);
    __syncthreads();

    // ---- ctx accumulation: thread = dim, vectorized weight loads ----
    float a1 = 0.f, a2 = 0.f;
    const float* ie = item_emb + tid;
#pragma unroll 2
    for (int l4 = 0; l4 < LL / 4; ++l4) {
        float4 w1 = *reinterpret_cast<const float4*>(&sW1[l4 * 4]);
        float4 w2 = *reinterpret_cast<const float4*>(&sW2[l4 * 4]);
        int4   rr = *reinterpret_cast<const int4*>(&sRef[l4 * 4]);
        float v0 = __ldg(ie + (size_t)rr.x * DD);
        float v1 = __ldg(ie + (size_t)rr.y * DD);
        float v2 = __ldg(ie + (size_t)rr.z * DD);
        float v3 = __ldg(ie + (size_t)rr.w * DD);
        a1 = fmaf(w1.x, v0, a1); a2 = fmaf(w2.x, v0, a2);
        a1 = fmaf(w1.y, v1, a1); a2 = fmaf(w2.y, v1, a2);
        a1 = fmaf(w1.z, v2, a1); a2 = fmaf(w2.z, v2, a2);
        a1 = fmaf(w1.w, v3, a1); a2 = fmaf(w2.w, v3, a2);
    }
    a1 *= i1; a2 *= i2;

    // ---- epilogue: 2x layernorm + GMF fuse + prediction head ----
    float pu   = a1 * sQ[tid];
    float mean = block_sum(pu, sRed) * (1.f / DD);
    float dmu  = pu - mean;
    float var  = block_sum(dmu * dmu, sRed) * (1.f / DD);
    float us   = fmaf(dmu * rsqrtf(var + 1e-5f), ln_u_g[tid], ln_u_b[tid]);

    float pi    = a2 * __ldg(&item_emb[(size_t)t * DD + tid]);
    float mean2 = block_sum(pi, sRed) * (1.f / DD);
    float dmi   = pi - mean2;
    float var2  = block_sum(dmi * dmi, sRed) * (1.f / DD);
    float is    = fmaf(dmi * rsqrtf(var2 + 1e-5f), ln_i_g[tid], ln_i_b[tid]);

    float tot = block_sum(us * is * pred_W[tid], sRed);
    if (tid == 0) out[b] = tot + pred_b[0];
}

// ---------------- kernel 3: deterministic KL reduction ----------------------
__global__ __launch_bounds__(256) void finalize_kernel(float* out, int B, int out_idx) {
    __shared__ float sk[8], sn[8];
    int tid = threadIdx.x;
    float k = 0.f, n = 0.f;
    for (int i = tid; i < B; i += 256) { k += g_klsum[i]; n += g_nvalid[i]; }
#pragma unroll
    for (int o = 16; o; o >>= 1) {
        k += __shfl_xor_sync(0xffffffffu, k, o);
        n += __shfl_xor_sync(0xffffffffu, n, o);
    }
    if ((tid & 31) == 0) { sk[tid >> 5] = k; sn[tid >> 5] = n; }
    __syncthreads();
    if (tid == 0) {
        float kt = 0.f, nt = 0.f;
#pragma unroll
        for (int i = 0; i < 8; ++i) { kt += sk[i]; nt += sn[i]; }
        out[out_idx] = 0.25f * kt / fmaxf(nt, 1.f);
    }
}

// ---------------- launch ----------------------------------------------------
extern "C" void kernel_launch(void* const* d_in, const int* in_sizes, int n_in,
                              void* d_out, int out_size)
{
    const float* user_emb = (const float*)d_in[0];
    const float* item_emb = (const float*)d_in[1];
    const float* Wq       = (const float*)d_in[2];
    const float* Wk       = (const float*)d_in[3];
    const float* b_att    = (const float*)d_in[4];
    const float* v_att    = (const float*)d_in[5];
    const float* ln_u_g   = (const float*)d_in[6];
    const float* ln_u_b   = (const float*)d_in[7];
    const float* ln_i_g   = (const float*)d_in[8];
    const float* ln_i_b   = (const float*)d_in[9];
    const float* pred_W   = (const float*)d_in[10];
    const float* pred_b   = (const float*)d_in[11];
    const int*   user_hist= (const int*)d_in[12];
    const int*   user_idx = (const int*)d_in[13];
    const int*   item_idx = (const int*)d_in[14];

    int B      = in_sizes[13];
    int n_rows = in_sizes[1] / DD;      // 100001
    int pad_id = n_rows - 1;

    cudaFuncSetAttribute(kw_mma_kernel,
                         cudaFuncAttributeMaxDynamicSharedMemorySize, KW_SMEM_BYTES);
    cudaFuncSetAttribute(qw_mma_kernel,
                         cudaFuncAttributeMaxDynamicSharedMemorySize, KW_SMEM_BYTES);

    kw_mma_kernel<<<(n_rows + MB - 1) / MB, 256, KW_SMEM_BYTES>>>(item_emb, Wk, n_rows);
    qw_mma_kernel<<<(B + MB - 1) / MB, 256, KW_SMEM_BYTES>>>(user_emb, Wq, b_att,
                                                             user_idx, B);
    main_kernel<<<B, 128>>>(user_emb, item_emb, v_att,
                            ln_u_g, ln_u_b, ln_i_g, ln_i_b, pred_W, pred_b,
                            user_hist, user_idx, item_idx, (float*)d_out, pad_id);
    if (out_size > B)
        finalize_kernel<<<1, 256>>>((float*)d_out, B, out_size - 1);
}

// round 6
// speedup vs baseline: 1.9273x; 1.0621x over previous
#include <cuda_runtime.h>
#include <cuda_bf16.h>
#include <stdint.h>

#define DD 128
#define LL 200

// ---------------- device scratch (static globals: allocation-free) ----------
__device__ __nv_bfloat16 g_kWh[(size_t)100001 * DD];  // (item_emb @ Wk) in bf16
__device__ float g_qWb[(size_t)8192 * DD];            // user_emb[uidx]@Wq + b_att
__device__ float g_klsum[8192];
__device__ float g_nvalid[8192];
__device__ int   g_ctr;                               // self-resetting counter

__device__ __forceinline__ float cvt_tf32(float x) {
    float r; asm("cvt.rna.tf32.f32 %0, %1;" : "=f"(r) : "f"(x)); return r;
}
__device__ __forceinline__ float tanh_hw(float x) {
    float t; asm("tanh.approx.f32 %0, %1;" : "=f"(t) : "f"(x)); return t;
}

// ---------------- mma tile core: C[64x128] = A[64x128] @ B^T ----------------
#define TS 132
#define MB 64
#define KW_SMEM_BYTES ((MB + 128) * TS * 4)

template <bool GATHER, bool STORE_BF16>
__device__ __forceinline__ void mma_tile(
    const float* __restrict__ Arows, const int* __restrict__ gidx,
    const float* __restrict__ Wmat, const float* __restrict__ bias,
    void* __restrict__ Cout, size_t base, int n_rows, float* smem)
{
    float* As = smem;                 // [MB][TS]
    float* Bs = smem + MB * TS;       // [128][TS] (n-major)
    int tid = threadIdx.x, lane = tid & 31, warp = tid >> 5;

    const float4* A4 = reinterpret_cast<const float4*>(Arows);
#pragma unroll
    for (int j = 0; j < 8; ++j) {
        int f = tid + j * 256;            // 0..2047 float4s
        int m = f >> 5, kc = f & 31;
        size_t gi = base + m; if (gi >= (size_t)n_rows) gi = n_rows - 1;
        if (GATHER) gi = (size_t)gidx[gi];
        float4 v = A4[gi * 32 + kc];
        v.x = cvt_tf32(v.x); v.y = cvt_tf32(v.y);
        v.z = cvt_tf32(v.z); v.w = cvt_tf32(v.w);
        *reinterpret_cast<float4*>(&As[m * TS + kc * 4]) = v;
    }
#pragma unroll
    for (int j = 0; j < 64; ++j) {
        int f = tid + j * 256;            // 0..16383
        int k = f >> 7, n = f & 127;
        Bs[n * TS + k] = cvt_tf32(__ldg(&Wmat[k * 128 + n]));
    }
    __syncthreads();

    int gq = lane >> 2, qt = lane & 3;
    int mrow = (warp >> 1) * 16;
    int ncol = (warp & 1) * 64;

    float c[8][4];
#pragma unroll
    for (int nt = 0; nt < 8; ++nt)
#pragma unroll
        for (int i = 0; i < 4; ++i) c[nt][i] = 0.f;

    const float* Ar0 = &As[(mrow + gq) * TS + qt];
    const float* Ar1 = Ar0 + 8 * TS;
    const float* Bq  = &Bs[(ncol + gq) * TS + qt];

#pragma unroll
    for (int ks = 0; ks < 16; ++ks) {
        int k0 = ks * 8;
        uint32_t a0 = __float_as_uint(Ar0[k0]);
        uint32_t a1 = __float_as_uint(Ar1[k0]);
        uint32_t a2 = __float_as_uint(Ar0[k0 + 4]);
        uint32_t a3 = __float_as_uint(Ar1[k0 + 4]);
#pragma unroll
        for (int nt = 0; nt < 8; ++nt) {
            uint32_t b0 = __float_as_uint(Bq[nt * 8 * TS + k0]);
            uint32_t b1 = __float_as_uint(Bq[nt * 8 * TS + k0 + 4]);
            asm volatile(
                "mma.sync.aligned.m16n8k8.row.col.f32.tf32.tf32.f32 "
                "{%0,%1,%2,%3}, {%4,%5,%6,%7}, {%8,%9}, {%0,%1,%2,%3};"
                : "+f"(c[nt][0]), "+f"(c[nt][1]), "+f"(c[nt][2]), "+f"(c[nt][3])
                : "r"(a0), "r"(a1), "r"(a2), "r"(a3), "r"(b0), "r"(b1));
        }
    }

    size_t g0 = base + mrow + gq;
    bool ok0 = g0 < (size_t)n_rows, ok1 = (g0 + 8) < (size_t)n_rows;
#pragma unroll
    for (int nt = 0; nt < 8; ++nt) {
        int col = ncol + nt * 8 + qt * 2;
        float bx = bias ? __ldg(&bias[col]) : 0.f;
        float by = bias ? __ldg(&bias[col + 1]) : 0.f;
        if (STORE_BF16) {
            __nv_bfloat16* Ch = reinterpret_cast<__nv_bfloat16*>(Cout);
            if (ok0) *reinterpret_cast<__nv_bfloat162*>(&Ch[g0 * 128 + col])
                         = __floats2bfloat162_rn(c[nt][0] + bx, c[nt][1] + by);
            if (ok1) *reinterpret_cast<__nv_bfloat162*>(&Ch[(g0 + 8) * 128 + col])
                         = __floats2bfloat162_rn(c[nt][2] + bx, c[nt][3] + by);
        } else {
            float* Cf = reinterpret_cast<float*>(Cout);
            if (ok0) *reinterpret_cast<float2*>(&Cf[g0 * 128 + col])
                         = make_float2(c[nt][0] + bx, c[nt][1] + by);
            if (ok1) *reinterpret_cast<float2*>(&Cf[(g0 + 8) * 128 + col])
                         = make_float2(c[nt][2] + bx, c[nt][3] + by);
        }
    }
}

__global__ __launch_bounds__(256, 2) void kw_mma_kernel(
    const float* __restrict__ item_emb, const float* __restrict__ Wk, int n_rows)
{
    extern __shared__ float smem[];
    mma_tile<false, true>(item_emb, nullptr, Wk, nullptr, g_kWh,
                          (size_t)blockIdx.x * MB, n_rows, smem);
}

__global__ __launch_bounds__(256, 2) void qw_mma_kernel(
    const float* __restrict__ user_emb, const float* __restrict__ Wq,
    const float* __restrict__ b_att, const int* __restrict__ user_idx, int B)
{
    extern __shared__ float smem[];
    mma_tile<true, false>(user_emb, user_idx, Wq, b_att, g_qWb,
                          (size_t)blockIdx.x * MB, B, smem);
}

// ---------------- threefry2x32 (JAX-compatible) -----------------------------
__device__ __forceinline__ uint32_t rotl32(uint32_t x, int r) {
    return (x << r) | (x >> (32 - r));
}
__device__ __forceinline__ uint32_t threefry32(uint32_t k0, uint32_t k1,
                                               uint32_t x0, uint32_t x1) {
    uint32_t ks2 = k0 ^ k1 ^ 0x1BD11BDAu;
    x0 += k0; x1 += k1;
#define TFR(r) { x0 += x1; x1 = rotl32(x1, r); x1 ^= x0; }
    TFR(13) TFR(15) TFR(26) TFR(6)   x0 += k1;  x1 += ks2 + 1u;
    TFR(17) TFR(29) TFR(16) TFR(24)  x0 += ks2; x1 += k0 + 2u;
    TFR(13) TFR(15) TFR(26) TFR(6)   x0 += k0;  x1 += k1 + 3u;
    TFR(17) TFR(29) TFR(16) TFR(24)  x0 += k1;  x1 += ks2 + 4u;
    TFR(13) TFR(15) TFR(26) TFR(6)   x0 += ks2; x1 += k0 + 5u;
#undef TFR
    return x0 ^ x1;
}
__device__ __forceinline__ float jax_normal_from_bits(uint32_t bits) {
    float f = __uint_as_float((bits >> 9) | 0x3F800000u) - 1.0f;
    const float lo = -0.99999994f;
    float u = fmaf(f, 1.0f - lo, lo);
    u = fmaxf(lo, u);
    return 1.41421356f * erfinvf(u);
}

// ---------------- fused multi-value block reductions (128 threads) ----------
__device__ __forceinline__ void block_sum2(float& a, float& b, float* sR) {
#pragma unroll
    for (int o = 16; o; o >>= 1) {
        a += __shfl_xor_sync(0xffffffffu, a, o);
        b += __shfl_xor_sync(0xffffffffu, b, o);
    }
    int warp = threadIdx.x >> 5;
    __syncthreads();
    if ((threadIdx.x & 31) == 0) { sR[warp] = a; sR[4 + warp] = b; }
    __syncthreads();
    a = (sR[0] + sR[1]) + (sR[2] + sR[3]);
    b = (sR[4] + sR[5]) + (sR[6] + sR[7]);
}
__device__ __forceinline__ void block_sum3(float& a, float& b, float& c, float* sR) {
#pragma unroll
    for (int o = 16; o; o >>= 1) {
        a += __shfl_xor_sync(0xffffffffu, a, o);
        b += __shfl_xor_sync(0xffffffffu, b, o);
        c += __shfl_xor_sync(0xffffffffu, c, o);
    }
    int warp = threadIdx.x >> 5;
    __syncthreads();
    if ((threadIdx.x & 31) == 0) { sR[warp] = a; sR[4 + warp] = b; sR[8 + warp] = c; }
    __syncthreads();
    a = (sR[0] + sR[1]) + (sR[2] + sR[3]);
    b = (sR[4] + sR[5]) + (sR[6] + sR[7]);
    c = (sR[8] + sR[9]) + (sR[10] + sR[11]);
}
__device__ __forceinline__ void block_sum4(float& a, float& b, float& c, float& d,
                                           float* sR) {
#pragma unroll
    for (int o = 16; o; o >>= 1) {
        a += __shfl_xor_sync(0xffffffffu, a, o);
        b += __shfl_xor_sync(0xffffffffu, b, o);
        c += __shfl_xor_sync(0xffffffffu, c, o);
        d += __shfl_xor_sync(0xffffffffu, d, o);
    }
    int warp = threadIdx.x >> 5;
    __syncthreads();
    if ((threadIdx.x & 31) == 0) {
        sR[warp] = a; sR[4 + warp] = b; sR[8 + warp] = c; sR[12 + warp] = d;
    }
    __syncthreads();
    a = (sR[0]  + sR[1])  + (sR[2]  + sR[3]);
    b = (sR[4]  + sR[5])  + (sR[6]  + sR[7]);
    c = (sR[8]  + sR[9])  + (sR[10] + sR[11]);
    d = (sR[12] + sR[13]) + (sR[14] + sR[15]);
}
__device__ __forceinline__ float block_sum1(float v, float* sR) {
#pragma unroll
    for (int o = 16; o; o >>= 1) v += __shfl_xor_sync(0xffffffffu, v, o);
    __syncthreads();
    if ((threadIdx.x & 31) == 0) sR[threadIdx.x >> 5] = v;
    __syncthreads();
    return (sR[0] + sR[1]) + (sR[2] + sR[3]);
}

// ---------------- kernel 2: fused BAM + epilogue + last-block KL ------------
__global__ __launch_bounds__(128) void main_kernel(
    const float* __restrict__ user_emb, const float* __restrict__ item_emb,
    const float* __restrict__ v_att,
    const float* __restrict__ ln_u_g,   const float* __restrict__ ln_u_b,
    const float* __restrict__ ln_i_g,   const float* __restrict__ ln_i_b,
    const float* __restrict__ pred_W,   const float* __restrict__ pred_b,
    const int*   __restrict__ user_hist,const int*  __restrict__ user_idx,
    const int*   __restrict__ item_idx, float* __restrict__ out, int pad_id,
    int B, int out_idx)
{
    __shared__ float sQ[DD];
    __shared__ int   sRef[LL], sMask[LL];
    __shared__ float sS[LL], sW1[LL], sW2[LL];
    __shared__ float sRed[16];
    __shared__ int   sLast;

    int b = blockIdx.x, tid = threadIdx.x;
    int u = user_idx[b], t = item_idx[b];

    for (int l = tid; l < LL; l += 128) {
        int r = user_hist[(size_t)u * LL + l];
        sRef[l]  = r;
        sMask[l] = (r != t) && (r != pad_id);
    }
    sQ[tid] = user_emb[(size_t)u * DD + tid];
    __syncthreads();

    int lane = tid & 31, warp = tid >> 5;

    // ---- scores: warp handles 2 l per iter; 16 lanes x 8 dims (bf16 kW) ----
    {
        int half = lane >> 4, hl = lane & 15;
        int d0 = hl * 8;
        const float* qp = &g_qWb[(size_t)b * DD + d0];
        float4 qa = *reinterpret_cast<const float4*>(qp);
        float4 qb = *reinterpret_cast<const float4*>(qp + 4);
        float4 va = __ldg(reinterpret_cast<const float4*>(&v_att[d0]));
        float4 vb = __ldg(reinterpret_cast<const float4*>(&v_att[d0 + 4]));
        int lbase = warp * 2 + half;
#pragma unroll 2
        for (int i = 0; i < 25; ++i) {
            int l = lbase + i * 8;
            bool mk = sMask[l] != 0;
            float p = 0.f;
            if (mk) {
                uint4 kv = __ldg(reinterpret_cast<const uint4*>(
                    &g_kWh[(size_t)sRef[l] * DD + d0]));
                float2 f0 = __bfloat1622float2(*reinterpret_cast<__nv_bfloat162*>(&kv.x));
                float2 f1 = __bfloat1622float2(*reinterpret_cast<__nv_bfloat162*>(&kv.y));
                float2 f2 = __bfloat1622float2(*reinterpret_cast<__nv_bfloat162*>(&kv.z));
                float2 f3 = __bfloat1622float2(*reinterpret_cast<__nv_bfloat162*>(&kv.w));
                p =      tanh_hw(qa.x + f0.x) * va.x;
                p = fmaf(tanh_hw(qa.y + f0.y), va.y, p);
                p = fmaf(tanh_hw(qa.z + f1.x), va.z, p);
                p = fmaf(tanh_hw(qa.w + f1.y), va.w, p);
                p = fmaf(tanh_hw(qb.x + f2.x), vb.x, p);
                p = fmaf(tanh_hw(qb.y + f2.y), vb.y, p);
                p = fmaf(tanh_hw(qb.z + f3.x), vb.z, p);
                p = fmaf(tanh_hw(qb.w + f3.y), vb.w, p);
            }
#pragma unroll
            for (int o = 8; o; o >>= 1) p += __shfl_xor_sync(0xffffffffu, p, o);
            if (hl == 0) sS[l] = mk ? p * 0.25f : -1e9f;
        }
    }
    __syncthreads();

    // ---- masked softmax ----
    float m = -3e38f;
    for (int l = tid; l < LL; l += 128) m = fmaxf(m, sS[l]);
#pragma unroll
    for (int o = 16; o; o >>= 1) m = fmaxf(m, __shfl_xor_sync(0xffffffffu, m, o));
    __syncthreads();
    if (lane == 0) sRed[warp] = m;
    __syncthreads();
    m = fmaxf(fmaxf(sRed[0], sRed[1]), fmaxf(sRed[2], sRed[3]));

    float esum = 0.f, cnt = 0.f;
    for (int l = tid; l < LL; l += 128) {
        float e = __expf(sS[l] - m);
        sS[l] = e; esum += e;
        if (sMask[l]) cnt += 1.f;
    }
    block_sum2(esum, cnt, sRed);
    float nv   = fmaxf(cnt, 1.f);
    float mu_p = -__logf(nv);
    float invE = 1.f / esum;

    // ---- sampled weights (two draws, shared alpha) + KL ----
    float klacc = 0.f, ws1 = 0.f, ws2 = 0.f;
    uint32_t b200 = (uint32_t)b * LL;
    for (int l = tid; l < LL; l += 128) {
        float w1 = 0.f, w2 = 0.f;
        if (sMask[l]) {
            float a  = fmaf(sS[l], invE, 1e-24f);
            float mu = __logf(a);
            float dd = mu - mu_p;
            klacc += 1.8075851f + dd * dd * 0.5f;
            uint32_t idx = b200 + (uint32_t)l;
            float e1 = jax_normal_from_bits(threefry32(0u, 1u, 0u, idx));
            float e2 = jax_normal_from_bits(threefry32(0u, 2u, 0u, idx));
            w1 = a * __expf(0.1f * e1);
            w2 = a * __expf(0.1f * e2);
        }
        sW1[l] = w1; sW2[l] = w2; ws1 += w1; ws2 += w2;
    }
    block_sum3(klacc, ws1, ws2, sRed);
    if (tid == 0) { g_klsum[b] = klacc; g_nvalid[b] = cnt; }
    float i1 = 1.f / (ws1 + 1e-12f), i2 = 1.f / (ws2 + 1e-12f);
    __syncthreads();

    // ---- ctx accumulation: thread = dim, vectorized weight loads ----
    float a1 = 0.f, a2 = 0.f;
    const float* ie = item_emb + tid;
#pragma unroll 2
    for (int l4 = 0; l4 < LL / 4; ++l4) {
        float4 w1 = *reinterpret_cast<const float4*>(&sW1[l4 * 4]);
        float4 w2 = *reinterpret_cast<const float4*>(&sW2[l4 * 4]);
        int4   rr = *reinterpret_cast<const int4*>(&sRef[l4 * 4]);
        float v0 = __ldg(ie + (size_t)rr.x * DD);
        float v1 = __ldg(ie + (size_t)rr.y * DD);
        float v2 = __ldg(ie + (size_t)rr.z * DD);
        float v3 = __ldg(ie + (size_t)rr.w * DD);
        a1 = fmaf(w1.x, v0, a1); a2 = fmaf(w2.x, v0, a2);
        a1 = fmaf(w1.y, v1, a1); a2 = fmaf(w2.y, v1, a2);
        a1 = fmaf(w1.z, v2, a1); a2 = fmaf(w2.z, v2, a2);
        a1 = fmaf(w1.w, v3, a1); a2 = fmaf(w2.w, v3, a2);
    }
    a1 *= i1; a2 *= i2;

    // ---- epilogue: 2x single-pass layernorm + GMF fuse + head ----
    float pu = a1 * sQ[tid];
    float pi = a2 * __ldg(&item_emb[(size_t)t * DD + tid]);
    float su = pu, squ = pu * pu, si = pi, sqi = pi * pi;
    block_sum4(su, squ, si, sqi, sRed);
    float mu_  = su * (1.f / DD);
    float var  = squ * (1.f / DD) - mu_ * mu_;
    float mi_  = si * (1.f / DD);
    float var2 = sqi * (1.f / DD) - mi_ * mi_;
    float us = fmaf((pu - mu_) * rsqrtf(var + 1e-5f),  ln_u_g[tid], ln_u_b[tid]);
    float is = fmaf((pi - mi_) * rsqrtf(var2 + 1e-5f), ln_i_g[tid], ln_i_b[tid]);

    float tot = block_sum1(us * is * pred_W[tid], sRed);
    if (tid == 0) out[b] = tot + pred_b[0];

    // ---- last-block deterministic KL finalize ----
    if (out_idx >= 0) {
        if (tid == 0) {
            __threadfence();
            sLast = (atomicAdd(&g_ctr, 1) == B - 1);
        }
        __syncthreads();
        if (sLast) {
            __threadfence();
            float k = 0.f, n = 0.f;
            for (int i = tid; i < B; i += 128) { k += g_klsum[i]; n += g_nvalid[i]; }
            block_sum2(k, n, sRed);
            if (tid == 0) {
                out[out_idx] = 0.25f * k / fmaxf(n, 1.f);
                g_ctr = 0;                       // reset for next graph replay
            }
        }
    }
}

// ---------------- launch ----------------------------------------------------
extern "C" void kernel_launch(void* const* d_in, const int* in_sizes, int n_in,
                              void* d_out, int out_size)
{
    const float* user_emb = (const float*)d_in[0];
    const float* item_emb = (const float*)d_in[1];
    const float* Wq       = (const float*)d_in[2];
    const float* Wk       = (const float*)d_in[3];
    const float* b_att    = (const float*)d_in[4];
    const float* v_att    = (const float*)d_in[5];
    const float* ln_u_g   = (const float*)d_in[6];
    const float* ln_u_b   = (const float*)d_in[7];
    const float* ln_i_g   = (const float*)d_in[8];
    const float* ln_i_b   = (const float*)d_in[9];
    const float* pred_W   = (const float*)d_in[10];
    const float* pred_b   = (const float*)d_in[11];
    const int*   user_hist= (const int*)d_in[12];
    const int*   user_idx = (const int*)d_in[13];
    const int*   item_idx = (const int*)d_in[14];

    int B      = in_sizes[13];
    int n_rows = in_sizes[1] / DD;      // 100001
    int pad_id = n_rows - 1;
    int out_idx = (out_size > B) ? (out_size - 1) : -1;

    cudaFuncSetAttribute(kw_mma_kernel,
                         cudaFuncAttributeMaxDynamicSharedMemorySize, KW_SMEM_BYTES);
    cudaFuncSetAttribute(qw_mma_kernel,
                         cudaFuncAttributeMaxDynamicSharedMemorySize, KW_SMEM_BYTES);

    kw_mma_kernel<<<(n_rows + MB - 1) / MB, 256, KW_SMEM_BYTES>>>(item_emb, Wk, n_rows);
    qw_mma_kernel<<<(B + MB - 1) / MB, 256, KW_SMEM_BYTES>>>(user_emb, Wq, b_att,
                                                             user_idx, B);
    main_kernel<<<B, 128>>>(user_emb, item_emb, v_att,
                            ln_u_g, ln_u_b, ln_i_g, ln_i_b, pred_W, pred_b,
                            user_hist, user_idx, item_idx, (float*)d_out, pad_id,
                            B, out_idx);
}

// round 8
// speedup vs baseline: 2.2255x; 1.1548x over previous
#include <cuda_runtime.h>
#include <cuda_bf16.h>
#include <stdint.h>

#define DD 128
#define LL 200

// ---------------- device scratch (static globals: allocation-free) ----------
__device__ __nv_bfloat16 g_kWh[(size_t)100001 * DD];  // (item_emb @ Wk) in bf16
__device__ __nv_bfloat16 g_WkT[DD * DD];              // Wk transposed, bf16
__device__ float g_qWb[(size_t)8192 * DD];            // user_emb[uidx]@Wq + b_att
__device__ float g_klsum[8192];
__device__ float g_nvalid[8192];
__device__ int   g_ctr;                               // self-resetting counter

__device__ __forceinline__ float cvt_tf32(float x) {
    float r; asm("cvt.rna.tf32.f32 %0, %1;" : "=f"(r) : "f"(x)); return r;
}
__device__ __forceinline__ float tanh_hw(float x) {
    float t; asm("tanh.approx.f32 %0, %1;" : "=f"(t) : "f"(x)); return t;
}

// ---------------- kernel 0: transpose Wk -> bf16 ----------------------------
__global__ __launch_bounds__(256) void wkt_kernel(const float* __restrict__ Wk)
{
    __shared__ float tile[32][33];
    int bx = (blockIdx.x & 3) * 32;     // n tile
    int by = (blockIdx.x >> 2) * 32;    // k tile
    int tx = threadIdx.x & 31, ty = threadIdx.x >> 5;  // ty 0..7
#pragma unroll
    for (int j = 0; j < 4; ++j)
        tile[ty + j * 8][tx] = Wk[(by + ty + j * 8) * DD + bx + tx];
    __syncthreads();
#pragma unroll
    for (int j = 0; j < 4; ++j)
        g_WkT[(bx + ty + j * 8) * DD + by + tx] =
            __float2bfloat16(tile[tx][ty + j * 8]);
}

// ---------------- kernel 1a: kW via bf16 mma m16n8k16 -----------------------
// Block 256 thr: tile M=128 x N=128 x K=128. Warp tile M32 x N64 (4m x 2n).
// A, B in bf16 smem, rows padded to 136 elements (272B) -> conflict-free frags.
#define TSH 136
#define KW_SMEM_BYTES (2 * 128 * TSH * 2)

__global__ __launch_bounds__(256, 2) void kw_mma_kernel(
    const float* __restrict__ item_emb, int n_rows)
{
    extern __shared__ __nv_bfloat16 sh[];
    __nv_bfloat16* As = sh;                 // [128][TSH]
    __nv_bfloat16* Bs = sh + 128 * TSH;     // [128][TSH] (n-major)
    int tid = threadIdx.x, lane = tid & 31, warp = tid >> 5;
    size_t base = (size_t)blockIdx.x * 128;

    // A fill: coalesced float4 reads -> bf16x4 stores (conflict-free)
    const float4* A4 = reinterpret_cast<const float4*>(item_emb);
#pragma unroll
    for (int j = 0; j < 16; ++j) {
        int f = tid + j * 256;              // 0..4095
        int m = f >> 5, kc = f & 31;        // kc: float4 index (4 k)
        size_t gi = base + m; if (gi >= (size_t)n_rows) gi = n_rows - 1;
        float4 v = A4[gi * 32 + kc];
        __nv_bfloat162 lo = __floats2bfloat162_rn(v.x, v.y);
        __nv_bfloat162 hi = __floats2bfloat162_rn(v.z, v.w);
        *reinterpret_cast<uint2*>(&As[m * TSH + kc * 4]) =
            make_uint2(*reinterpret_cast<uint32_t*>(&lo),
                       *reinterpret_cast<uint32_t*>(&hi));
    }
    // B fill: coalesced uint4 copy of pre-transposed bf16 Wk (conflict-free)
    const uint4* W4 = reinterpret_cast<const uint4*>(g_WkT);
#pragma unroll
    for (int j = 0; j < 8; ++j) {
        int f = tid + j * 256;              // 0..2047 uint4 (8 bf16)
        int n = f >> 4, kc = f & 15;
        *reinterpret_cast<uint4*>(&Bs[n * TSH + kc * 8]) = W4[f];
    }
    __syncthreads();

    int gq = lane >> 2, tg = lane & 3, tg2 = tg * 2;
    int mrow = (warp >> 1) * 32;
    int ncol = (warp & 1) * 64;

    float c[2][8][4];
#pragma unroll
    for (int mi = 0; mi < 2; ++mi)
#pragma unroll
        for (int nt = 0; nt < 8; ++nt)
#pragma unroll
            for (int i = 0; i < 4; ++i) c[mi][nt][i] = 0.f;

#pragma unroll
    for (int ks = 0; ks < 8; ++ks) {
        int k0 = ks * 16;
        uint32_t bq[8][2];
#pragma unroll
        for (int nt = 0; nt < 8; ++nt) {
            const __nv_bfloat16* bp = &Bs[(ncol + nt * 8 + gq) * TSH + k0 + tg2];
            bq[nt][0] = *reinterpret_cast<const uint32_t*>(bp);
            bq[nt][1] = *reinterpret_cast<const uint32_t*>(bp + 8);
        }
#pragma unroll
        for (int mi = 0; mi < 2; ++mi) {
            const __nv_bfloat16* ap0 = &As[(mrow + mi * 16 + gq) * TSH + k0 + tg2];
            const __nv_bfloat16* ap1 = ap0 + 8 * TSH;
            uint32_t a0 = *reinterpret_cast<const uint32_t*>(ap0);
            uint32_t a1 = *reinterpret_cast<const uint32_t*>(ap1);
            uint32_t a2 = *reinterpret_cast<const uint32_t*>(ap0 + 8);
            uint32_t a3 = *reinterpret_cast<const uint32_t*>(ap1 + 8);
#pragma unroll
            for (int nt = 0; nt < 8; ++nt) {
                asm volatile(
                    "mma.sync.aligned.m16n8k16.row.col.f32.bf16.bf16.f32 "
                    "{%0,%1,%2,%3}, {%4,%5,%6,%7}, {%8,%9}, {%0,%1,%2,%3};"
                    : "+f"(c[mi][nt][0]), "+f"(c[mi][nt][1]),
                      "+f"(c[mi][nt][2]), "+f"(c[mi][nt][3])
                    : "r"(a0), "r"(a1), "r"(a2), "r"(a3),
                      "r"(bq[nt][0]), "r"(bq[nt][1]));
            }
        }
    }

#pragma unroll
    for (int mi = 0; mi < 2; ++mi) {
        size_t g0 = base + mrow + mi * 16 + gq;
        bool ok0 = g0 < (size_t)n_rows, ok1 = (g0 + 8) < (size_t)n_rows;
#pragma unroll
        for (int nt = 0; nt < 8; ++nt) {
            int col = ncol + nt * 8 + tg2;
            if (ok0) *reinterpret_cast<__nv_bfloat162*>(&g_kWh[g0 * DD + col])
                         = __floats2bfloat162_rn(c[mi][nt][0], c[mi][nt][1]);
            if (ok1) *reinterpret_cast<__nv_bfloat162*>(&g_kWh[(g0 + 8) * DD + col])
                         = __floats2bfloat162_rn(c[mi][nt][2], c[mi][nt][3]);
        }
    }
}

// ---------------- kernel 1b: qW via tf32 mma (fp32 out, gathered A) ---------
#define TS 132
#define MB 64
#define QW_SMEM_BYTES ((MB + 128) * TS * 4)

__global__ __launch_bounds__(256, 2) void qw_mma_kernel(
    const float* __restrict__ user_emb, const float* __restrict__ Wq,
    const float* __restrict__ b_att, const int* __restrict__ user_idx, int B)
{
    extern __shared__ float smemf[];
    float* As = smemf;
    float* Bs = smemf + MB * TS;
    int tid = threadIdx.x, lane = tid & 31, warp = tid >> 5;
    size_t base = (size_t)blockIdx.x * MB;

    const float4* A4 = reinterpret_cast<const float4*>(user_emb);
#pragma unroll
    for (int j = 0; j < 8; ++j) {
        int f = tid + j * 256;
        int m = f >> 5, kc = f & 31;
        size_t gi = base + m; if (gi >= (size_t)B) gi = B - 1;
        gi = (size_t)user_idx[gi];
        float4 v = A4[gi * 32 + kc];
        v.x = cvt_tf32(v.x); v.y = cvt_tf32(v.y);
        v.z = cvt_tf32(v.z); v.w = cvt_tf32(v.w);
        *reinterpret_cast<float4*>(&As[m * TS + kc * 4]) = v;
    }
#pragma unroll
    for (int j = 0; j < 64; ++j) {
        int f = tid + j * 256;
        int k = f >> 7, n = f & 127;
        Bs[n * TS + k] = cvt_tf32(__ldg(&Wq[k * 128 + n]));
    }
    __syncthreads();

    int gq = lane >> 2, qt = lane & 3;
    int mrow = (warp >> 1) * 16;
    int ncol = (warp & 1) * 64;

    float c[8][4];
#pragma unroll
    for (int nt = 0; nt < 8; ++nt)
#pragma unroll
        for (int i = 0; i < 4; ++i) c[nt][i] = 0.f;

    const float* Ar0 = &As[(mrow + gq) * TS + qt];
    const float* Ar1 = Ar0 + 8 * TS;
    const float* Bq  = &Bs[(ncol + gq) * TS + qt];

#pragma unroll
    for (int ks = 0; ks < 16; ++ks) {
        int k0 = ks * 8;
        uint32_t a0 = __float_as_uint(Ar0[k0]);
        uint32_t a1 = __float_as_uint(Ar1[k0]);
        uint32_t a2 = __float_as_uint(Ar0[k0 + 4]);
        uint32_t a3 = __float_as_uint(Ar1[k0 + 4]);
#pragma unroll
        for (int nt = 0; nt < 8; ++nt) {
            uint32_t b0 = __float_as_uint(Bq[nt * 8 * TS + k0]);
            uint32_t b1 = __float_as_uint(Bq[nt * 8 * TS + k0 + 4]);
            asm volatile(
                "mma.sync.aligned.m16n8k8.row.col.f32.tf32.tf32.f32 "
                "{%0,%1,%2,%3}, {%4,%5,%6,%7}, {%8,%9}, {%0,%1,%2,%3};"
                : "+f"(c[nt][0]), "+f"(c[nt][1]), "+f"(c[nt][2]), "+f"(c[nt][3])
                : "r"(a0), "r"(a1), "r"(a2), "r"(a3), "r"(b0), "r"(b1));
        }
    }

    size_t g0 = base + mrow + gq;
    bool ok0 = g0 < (size_t)B, ok1 = (g0 + 8) < (size_t)B;
#pragma unroll
    for (int nt = 0; nt < 8; ++nt) {
        int col = ncol + nt * 8 + qt * 2;
        float bx = __ldg(&b_att[col]);
        float by = __ldg(&b_att[col + 1]);
        if (ok0) *reinterpret_cast<float2*>(&g_qWb[g0 * DD + col])
                     = make_float2(c[nt][0] + bx, c[nt][1] + by);
        if (ok1) *reinterpret_cast<float2*>(&g_qWb[(g0 + 8) * DD + col])
                     = make_float2(c[nt][2] + bx, c[nt][3] + by);
    }
}

// ---------------- threefry2x32 (JAX-compatible) -----------------------------
__device__ __forceinline__ uint32_t rotl32(uint32_t x, int r) {
    return (x << r) | (x >> (32 - r));
}
__device__ __forceinline__ uint32_t threefry32(uint32_t k0, uint32_t k1,
                                               uint32_t x0, uint32_t x1) {
    uint32_t ks2 = k0 ^ k1 ^ 0x1BD11BDAu;
    x0 += k0; x1 += k1;
#define TFR(r) { x0 += x1; x1 = rotl32(x1, r); x1 ^= x0; }
    TFR(13) TFR(15) TFR(26) TFR(6)   x0 += k1;  x1 += ks2 + 1u;
    TFR(17) TFR(29) TFR(16) TFR(24)  x0 += ks2; x1 += k0 + 2u;
    TFR(13) TFR(15) TFR(26) TFR(6)   x0 += k0;  x1 += k1 + 3u;
    TFR(17) TFR(29) TFR(16) TFR(24)  x0 += k1;  x1 += ks2 + 4u;
    TFR(13) TFR(15) TFR(26) TFR(6)   x0 += ks2; x1 += k0 + 5u;
#undef TFR
    return x0 ^ x1;
}
__device__ __forceinline__ float jax_normal_from_bits(uint32_t bits) {
    float f = __uint_as_float((bits >> 9) | 0x3F800000u) - 1.0f;
    const float lo = -0.99999994f;
    float u = fmaf(f, 1.0f - lo, lo);
    u = fmaxf(lo, u);
    return 1.41421356f * erfinvf(u);
}

// ---------------- fused multi-value block reductions (128 threads) ----------
__device__ __forceinline__ void block_sum2(float& a, float& b, float* sR) {
#pragma unroll
    for (int o = 16; o; o >>= 1) {
        a += __shfl_xor_sync(0xffffffffu, a, o);
        b += __shfl_xor_sync(0xffffffffu, b, o);
    }
    int warp = threadIdx.x >> 5;
    __syncthreads();
    if ((threadIdx.x & 31) == 0) { sR[warp] = a; sR[4 + warp] = b; }
    __syncthreads();
    a = (sR[0] + sR[1]) + (sR[2] + sR[3]);
    b = (sR[4] + sR[5]) + (sR[6] + sR[7]);
}
__device__ __forceinline__ void block_sum3(float& a, float& b, float& c, float* sR) {
#pragma unroll
    for (int o = 16; o; o >>= 1) {
        a += __shfl_xor_sync(0xffffffffu, a, o);
        b += __shfl_xor_sync(0xffffffffu, b, o);
        c += __shfl_xor_sync(0xffffffffu, c, o);
    }
    int warp = threadIdx.x >> 5;
    __syncthreads();
    if ((threadIdx.x & 31) == 0) { sR[warp] = a; sR[4 + warp] = b; sR[8 + warp] = c; }
    __syncthreads();
    a = (sR[0] + sR[1]) + (sR[2] + sR[3]);
    b = (sR[4] + sR[5]) + (sR[6] + sR[7]);
    c = (sR[8] + sR[9]) + (sR[10] + sR[11]);
}
__device__ __forceinline__ void block_sum4(float& a, float& b, float& c, float& d,
                                           float* sR) {
#pragma unroll
    for (int o = 16; o; o >>= 1) {
        a += __shfl_xor_sync(0xffffffffu, a, o);
        b += __shfl_xor_sync(0xffffffffu, b, o);
        c += __shfl_xor_sync(0xffffffffu, c, o);
        d += __shfl_xor_sync(0xffffffffu, d, o);
    }
    int warp = threadIdx.x >> 5;
    __syncthreads();
    if ((threadIdx.x & 31) == 0) {
        sR[warp] = a; sR[4 + warp] = b; sR[8 + warp] = c; sR[12 + warp] = d;
    }
    __syncthreads();
    a = (sR[0]  + sR[1])  + (sR[2]  + sR[3]);
    b = (sR[4]  + sR[5])  + (sR[6]  + sR[7]);
    c = (sR[8]  + sR[9])  + (sR[10] + sR[11]);
    d = (sR[12] + sR[13]) + (sR[14] + sR[15]);
}
__device__ __forceinline__ float block_sum1(float v, float* sR) {
#pragma unroll
    for (int o = 16; o; o >>= 1) v += __shfl_xor_sync(0xffffffffu, v, o);
    __syncthreads();
    if ((threadIdx.x & 31) == 0) sR[threadIdx.x >> 5] = v;
    __syncthreads();
    return (sR[0] + sR[1]) + (sR[2] + sR[3]);
}

// ---------------- kernel 2: fused BAM + epilogue + last-block KL ------------
__global__ __launch_bounds__(128) void main_kernel(
    const float* __restrict__ user_emb, const float* __restrict__ item_emb,
    const float* __restrict__ v_att,
    const float* __restrict__ ln_u_g,   const float* __restrict__ ln_u_b,
    const float* __restrict__ ln_i_g,   const float* __restrict__ ln_i_b,
    const float* __restrict__ pred_W,   const float* __restrict__ pred_b,
    const int*   __restrict__ user_hist,const int*  __restrict__ user_idx,
    const int*   __restrict__ item_idx, float* __restrict__ out, int pad_id,
    int B, int out_idx)
{
    __shared__ float sQ[DD];
    __shared__ int   sOffI[LL], sMask[LL];     // byte offset r*512, valid mask
    __shared__ float sS[LL], sW1[LL], sW2[LL];
    __shared__ float sRed[16];
    __shared__ int   sLast;

    int b = blockIdx.x, tid = threadIdx.x;
    int u = user_idx[b], t = item_idx[b];

    for (int l = tid; l < LL; l += 128) {
        int r = user_hist[(size_t)u * LL + l];
        sOffI[l] = r << 9;                     // r * 128 dims * 4 bytes
        sMask[l] = (r != t) && (r != pad_id);
    }
    sQ[tid] = user_emb[(size_t)u * DD + tid];
    __syncthreads();

    int lane = tid & 31, warp = tid >> 5;

    // ---- scores: warp handles 2 l per iter; 16 lanes x 8 dims (bf16 kW) ----
    {
        int half = lane >> 4, hl = lane & 15;
        int d0 = hl * 8;
        const float* qp = &g_qWb[(size_t)b * DD + d0];
        float4 qa = *reinterpret_cast<const float4*>(qp);
        float4 qb = *reinterpret_cast<const float4*>(qp + 4);
        float4 va = __ldg(reinterpret_cast<const float4*>(&v_att[d0]));
        float4 vb = __ldg(reinterpret_cast<const float4*>(&v_att[d0 + 4]));
        const char* kb = reinterpret_cast<const char*>(g_kWh) + d0 * 2;
        int lbase = warp * 2 + half;
#pragma unroll 2
        for (int i = 0; i < 25; ++i) {
            int l = lbase + i * 8;
            bool mk = sMask[l] != 0;
            float p = 0.f;
            if (mk) {
                uint4 kv = __ldg(reinterpret_cast<const uint4*>(
                    kb + ((size_t)(uint32_t)sOffI[l] >> 1)));
                float2 f0 = __bfloat1622float2(*reinterpret_cast<__nv_bfloat162*>(&kv.x));
                float2 f1 = __bfloat1622float2(*reinterpret_cast<__nv_bfloat162*>(&kv.y));
                float2 f2 = __bfloat1622float2(*reinterpret_cast<__nv_bfloat162*>(&kv.z));
                float2 f3 = __bfloat1622float2(*reinterpret_cast<__nv_bfloat162*>(&kv.w));
                p =      tanh_hw(qa.x + f0.x) * va.x;
                p = fmaf(tanh_hw(qa.y + f0.y), va.y, p);
                p = fmaf(tanh_hw(qa.z + f1.x), va.z, p);
                p = fmaf(tanh_hw(qa.w + f1.y), va.w, p);
                p = fmaf(tanh_hw(qb.x + f2.x), vb.x, p);
                p = fmaf(tanh_hw(qb.y + f2.y), vb.y, p);
                p = fmaf(tanh_hw(qb.z + f3.x), vb.z, p);
                p = fmaf(tanh_hw(qb.w + f3.y), vb.w, p);
            }
#pragma unroll
            for (int o = 8; o; o >>= 1) p += __shfl_xor_sync(0xffffffffu, p, o);
            if (hl == 0) sS[l] = mk ? p * 0.25f : -1e9f;
        }
    }
    __syncthreads();

    // ---- masked softmax ----
    float m = -3e38f;
    for (int l = tid; l < LL; l += 128) m = fmaxf(m, sS[l]);
#pragma unroll
    for (int o = 16; o; o >>= 1) m = fmaxf(m, __shfl_xor_sync(0xffffffffu, m, o));
    __syncthreads();
    if (lane == 0) sRed[warp] = m;
    __syncthreads();
    m = fmaxf(fmaxf(sRed[0], sRed[1]), fmaxf(sRed[2], sRed[3]));

    float esum = 0.f, cnt = 0.f;
    for (int l = tid; l < LL; l += 128) {
        float e = __expf(sS[l] - m);
        sS[l] = e; esum += e;
        if (sMask[l]) cnt += 1.f;
    }
    block_sum2(esum, cnt, sRed);
    float nv   = fmaxf(cnt, 1.f);
    float mu_p = -__logf(nv);
    float invE = 1.f / esum;

    // ---- sampled weights (two draws, shared alpha) + KL ----
    float klacc = 0.f, ws1 = 0.f, ws2 = 0.f;
    uint32_t b200 = (uint32_t)b * LL;
    for (int l = tid; l < LL; l += 128) {
        float w1 = 0.f, w2 = 0.f;
        if (sMask[l]) {
            float a  = fmaf(sS[l], invE, 1e-24f);
            float mu = __logf(a);
            float dd = mu - mu_p;
            klacc += 1.8075851f + dd * dd * 0.5f;
            uint32_t idx = b200 + (uint32_t)l;
            float e1 = jax_normal_from_bits(threefry32(0u, 1u, 0u, idx));
            float e2 = jax_normal_from_bits(threefry32(0u, 2u, 0u, idx));
            w1 = a * __expf(0.1f * e1);
            w2 = a * __expf(0.1f * e2);
        }
        sW1[l] = w1; sW2[l] = w2; ws1 += w1; ws2 += w2;
    }
    block_sum3(klacc, ws1, ws2, sRed);
    if (tid == 0) { g_klsum[b] = klacc; g_nvalid[b] = cnt; }
    float i1 = 1.f / (ws1 + 1e-12f), i2 = 1.f / (ws2 + 1e-12f);
    __syncthreads();

    // ---- ctx accumulation: thread = dim, byte-offset gathers ----
    float a1 = 0.f, a2 = 0.f;
    const char* ieb = reinterpret_cast<const char*>(item_emb) + tid * 4;
#pragma unroll 2
    for (int l4 = 0; l4 < LL / 4; ++l4) {
        float4 w1 = *reinterpret_cast<const float4*>(&sW1[l4 * 4]);
        float4 w2 = *reinterpret_cast<const float4*>(&sW2[l4 * 4]);
        int4   rr = *reinterpret_cast<const int4*>(&sOffI[l4 * 4]);
        float v0 = __ldg(reinterpret_cast<const float*>(ieb + (size_t)(uint32_t)rr.x));
        float v1 = __ldg(reinterpret_cast<const float*>(ieb + (size_t)(uint32_t)rr.y));
        float v2 = __ldg(reinterpret_cast<const float*>(ieb + (size_t)(uint32_t)rr.z));
        float v3 = __ldg(reinterpret_cast<const float*>(ieb + (size_t)(uint32_t)rr.w));
        a1 = fmaf(w1.x, v0, a1); a2 = fmaf(w2.x, v0, a2);
        a1 = fmaf(w1.y, v1, a1); a2 = fmaf(w2.y, v1, a2);
        a1 = fmaf(w1.z, v2, a1); a2 = fmaf(w2.z, v2, a2);
        a1 = fmaf(w1.w, v3, a1); a2 = fmaf(w2.w, v3, a2);
    }
    a1 *= i1; a2 *= i2;

    // ---- epilogue: 2x single-pass layernorm + GMF fuse + head ----
    float pu = a1 * sQ[tid];
    float pi = a2 * __ldg(&item_emb[(size_t)t * DD + tid]);
    float su = pu, squ = pu * pu, si = pi, sqi = pi * pi;
    block_sum4(su, squ, si, sqi, sRed);
    float mu_  = su * (1.f / DD);
    float var  = squ * (1.f / DD) - mu_ * mu_;
    float mi_  = si * (1.f / DD);
    float var2 = sqi * (1.f / DD) - mi_ * mi_;
    float us = fmaf((pu - mu_) * rsqrtf(var + 1e-5f),  ln_u_g[tid], ln_u_b[tid]);
    float is = fmaf((pi - mi_) * rsqrtf(var2 + 1e-5f), ln_i_g[tid], ln_i_b[tid]);

    float tot = block_sum1(us * is * pred_W[tid], sRed);
    if (tid == 0) out[b] = tot + pred_b[0];

    // ---- last-block deterministic KL finalize ----
    if (out_idx >= 0) {
        if (tid == 0) {
            __threadfence();
            sLast = (atomicAdd(&g_ctr, 1) == B - 1);
        }
        __syncthreads();
        if (sLast) {
            __threadfence();
            float k = 0.f, n = 0.f;
            for (int i = tid; i < B; i += 128) { k += g_klsum[i]; n += g_nvalid[i]; }
            block_sum2(k, n, sRed);
            if (tid == 0) {
                out[out_idx] = 0.25f * k / fmaxf(n, 1.f);
                g_ctr = 0;
            }
        }
    }
}

// ---------------- launch ----------------------------------------------------
extern "C" void kernel_launch(void* const* d_in, const int* in_sizes, int n_in,
                              void* d_out, int out_size)
{
    const float* user_emb = (const float*)d_in[0];
    const float* item_emb = (const float*)d_in[1];
    const float* Wq       = (const float*)d_in[2];
    const float* Wk       = (const float*)d_in[3];
    const float* b_att    = (const float*)d_in[4];
    const float* v_att    = (const float*)d_in[5];
    const float* ln_u_g   = (const float*)d_in[6];
    const float* ln_u_b   = (const float*)d_in[7];
    const float* ln_i_g   = (const float*)d_in[8];
    const float* ln_i_b   = (const float*)d_in[9];
    const float* pred_W   = (const float*)d_in[10];
    const float* pred_b   = (const float*)d_in[11];
    const int*   user_hist= (const int*)d_in[12];
    const int*   user_idx = (const int*)d_in[13];
    const int*   item_idx = (const int*)d_in[14];

    int B      = in_sizes[13];
    int n_rows = in_sizes[1] / DD;      // 100001
    int pad_id = n_rows - 1;
    int out_idx = (out_size > B) ? (out_size - 1) : -1;

    cudaFuncSetAttribute(kw_mma_kernel,
                         cudaFuncAttributeMaxDynamicSharedMemorySize, KW_SMEM_BYTES);
    cudaFuncSetAttribute(qw_mma_kernel,
                         cudaFuncAttributeMaxDynamicSharedMemorySize, QW_SMEM_BYTES);

    wkt_kernel<<<16, 256>>>(Wk);
    kw_mma_kernel<<<(n_rows + 127) / 128, 256, KW_SMEM_BYTES>>>(item_emb, n_rows);
    qw_mma_kernel<<<(B + MB - 1) / MB, 256, QW_SMEM_BYTES>>>(user_emb, Wq, b_att,
                                                             user_idx, B);
    main_kernel<<<B, 128>>>(user_emb, item_emb, v_att,
                            ln_u_g, ln_u_b, ln_i_g, ln_i_b, pred_W, pred_b,
                            user_hist, user_idx, item_idx, (float*)d_out, pad_id,
                            B, out_idx);
}

// round 9
// speedup vs baseline: 2.4473x; 1.0997x over previous
#include <cuda_runtime.h>
#include <cuda_bf16.h>
#include <stdint.h>

#define DD 128
#define LL 200

// ---------------- device scratch (static globals: allocation-free) ----------
__device__ __nv_bfloat16 g_kWh[(size_t)100001 * DD];  // (item_emb @ Wk) in bf16
__device__ __nv_bfloat16 g_WkT[DD * DD];              // Wk^T, bf16
__device__ __nv_bfloat16 g_WqT[DD * DD];              // Wq^T, bf16
__device__ float g_qWb[(size_t)8192 * DD];            // user_emb[uidx]@Wq + b_att
__device__ float g_klsum[8192];
__device__ float g_nvalid[8192];
__device__ int   g_ctr;                               // self-resetting counter

__device__ __forceinline__ float tanh_hw(float x) {
    float t; asm("tanh.approx.f32 %0, %1;" : "=f"(t) : "f"(x)); return t;
}

// ---------------- kernel 0: transpose Wk, Wq -> bf16 ------------------------
__global__ __launch_bounds__(256) void wkt_kernel(
    const float* __restrict__ Wk, const float* __restrict__ Wq)
{
    __shared__ float tile[32][33];
    int which = blockIdx.x >> 4;
    int bi = blockIdx.x & 15;
    const float* src = which ? Wq : Wk;
    __nv_bfloat16* dst = which ? g_WqT : g_WkT;
    int bx = (bi & 3) * 32;             // n tile
    int by = (bi >> 2) * 32;            // k tile
    int tx = threadIdx.x & 31, ty = threadIdx.x >> 5;
#pragma unroll
    for (int j = 0; j < 4; ++j)
        tile[ty + j * 8][tx] = src[(by + ty + j * 8) * DD + bx + tx];
    __syncthreads();
#pragma unroll
    for (int j = 0; j < 4; ++j)
        dst[(bx + ty + j * 8) * DD + by + tx] =
            __float2bfloat16(tile[tx][ty + j * 8]);
}

// ---------------- bf16 mma tile: C[128x128] = A @ W^T -----------------------
#define TSH 136
#define GEMM_SMEM_BYTES (2 * 128 * TSH * 2)

template <bool GATHER, bool OUT_BF16>
__device__ __forceinline__ void mma_bf16_tile(
    const float* __restrict__ Arows, const int* __restrict__ gidx,
    const __nv_bfloat16* __restrict__ WT, const float* __restrict__ bias,
    void* __restrict__ Cout, size_t base, int n_rows, __nv_bfloat16* sh)
{
    __nv_bfloat16* As = sh;                 // [128][TSH]
    __nv_bfloat16* Bs = sh + 128 * TSH;     // [128][TSH] (n-major)
    int tid = threadIdx.x, lane = tid & 31, warp = tid >> 5;

    const float4* A4 = reinterpret_cast<const float4*>(Arows);
#pragma unroll
    for (int j = 0; j < 16; ++j) {
        int f = tid + j * 256;              // 0..4095
        int m = f >> 5, kc = f & 31;
        size_t gi = base + m; if (gi >= (size_t)n_rows) gi = n_rows - 1;
        if (GATHER) gi = (size_t)gidx[gi];
        float4 v = A4[gi * 32 + kc];
        __nv_bfloat162 lo = __floats2bfloat162_rn(v.x, v.y);
        __nv_bfloat162 hi = __floats2bfloat162_rn(v.z, v.w);
        *reinterpret_cast<uint2*>(&As[m * TSH + kc * 4]) =
            make_uint2(*reinterpret_cast<uint32_t*>(&lo),
                       *reinterpret_cast<uint32_t*>(&hi));
    }
    const uint4* W4 = reinterpret_cast<const uint4*>(WT);
#pragma unroll
    for (int j = 0; j < 8; ++j) {
        int f = tid + j * 256;              // 0..2047
        int n = f >> 4, kc = f & 15;
        *reinterpret_cast<uint4*>(&Bs[n * TSH + kc * 8]) = W4[f];
    }
    __syncthreads();

    int gq = lane >> 2, tg2 = (lane & 3) * 2;
    int mrow = (warp >> 1) * 32;
    int ncol = (warp & 1) * 64;

    float c[2][8][4];
#pragma unroll
    for (int mi = 0; mi < 2; ++mi)
#pragma unroll
        for (int nt = 0; nt < 8; ++nt)
#pragma unroll
            for (int i = 0; i < 4; ++i) c[mi][nt][i] = 0.f;

#pragma unroll
    for (int ks = 0; ks < 8; ++ks) {
        int k0 = ks * 16;
        uint32_t bq[8][2];
#pragma unroll
        for (int nt = 0; nt < 8; ++nt) {
            const __nv_bfloat16* bp = &Bs[(ncol + nt * 8 + gq) * TSH + k0 + tg2];
            bq[nt][0] = *reinterpret_cast<const uint32_t*>(bp);
            bq[nt][1] = *reinterpret_cast<const uint32_t*>(bp + 8);
        }
#pragma unroll
        for (int mi = 0; mi < 2; ++mi) {
            const __nv_bfloat16* ap0 = &As[(mrow + mi * 16 + gq) * TSH + k0 + tg2];
            const __nv_bfloat16* ap1 = ap0 + 8 * TSH;
            uint32_t a0 = *reinterpret_cast<const uint32_t*>(ap0);
            uint32_t a1 = *reinterpret_cast<const uint32_t*>(ap1);
            uint32_t a2 = *reinterpret_cast<const uint32_t*>(ap0 + 8);
            uint32_t a3 = *reinterpret_cast<const uint32_t*>(ap1 + 8);
#pragma unroll
            for (int nt = 0; nt < 8; ++nt) {
                asm volatile(
                    "mma.sync.aligned.m16n8k16.row.col.f32.bf16.bf16.f32 "
                    "{%0,%1,%2,%3}, {%4,%5,%6,%7}, {%8,%9}, {%0,%1,%2,%3};"
                    : "+f"(c[mi][nt][0]), "+f"(c[mi][nt][1]),
                      "+f"(c[mi][nt][2]), "+f"(c[mi][nt][3])
                    : "r"(a0), "r"(a1), "r"(a2), "r"(a3),
                      "r"(bq[nt][0]), "r"(bq[nt][1]));
            }
        }
    }

#pragma unroll
    for (int mi = 0; mi < 2; ++mi) {
        size_t g0 = base + mrow + mi * 16 + gq;
        bool ok0 = g0 < (size_t)n_rows, ok1 = (g0 + 8) < (size_t)n_rows;
#pragma unroll
        for (int nt = 0; nt < 8; ++nt) {
            int col = ncol + nt * 8 + tg2;
            if (OUT_BF16) {
                __nv_bfloat16* Ch = reinterpret_cast<__nv_bfloat16*>(Cout);
                if (ok0) *reinterpret_cast<__nv_bfloat162*>(&Ch[g0 * DD + col])
                             = __floats2bfloat162_rn(c[mi][nt][0], c[mi][nt][1]);
                if (ok1) *reinterpret_cast<__nv_bfloat162*>(&Ch[(g0 + 8) * DD + col])
                             = __floats2bfloat162_rn(c[mi][nt][2], c[mi][nt][3]);
            } else {
                float* Cf = reinterpret_cast<float*>(Cout);
                float bx = __ldg(&bias[col]);
                float by = __ldg(&bias[col + 1]);
                if (ok0) *reinterpret_cast<float2*>(&Cf[g0 * DD + col])
                             = make_float2(c[mi][nt][0] + bx, c[mi][nt][1] + by);
                if (ok1) *reinterpret_cast<float2*>(&Cf[(g0 + 8) * DD + col])
                             = make_float2(c[mi][nt][2] + bx, c[mi][nt][3] + by);
            }
        }
    }
}

// ---------------- kernel 1: merged kW + qW GEMMs ----------------------------
__global__ __launch_bounds__(256, 2) void gemm_kernel(
    const float* __restrict__ item_emb, const float* __restrict__ user_emb,
    const float* __restrict__ b_att, const int* __restrict__ user_idx,
    int n_rows, int B, int kwBlocks)
{
    extern __shared__ __nv_bfloat16 sh[];
    if ((int)blockIdx.x < kwBlocks) {
        mma_bf16_tile<false, true>(item_emb, nullptr, g_WkT, nullptr, g_kWh,
                                   (size_t)blockIdx.x * 128, n_rows, sh);
    } else {
        mma_bf16_tile<true, false>(user_emb, user_idx, g_WqT, b_att, g_qWb,
                                   (size_t)(blockIdx.x - kwBlocks) * 128, B, sh);
    }
}

// ---------------- threefry2x32 (JAX-compatible) -----------------------------
__device__ __forceinline__ uint32_t rotl32(uint32_t x, int r) {
    return (x << r) | (x >> (32 - r));
}
__device__ __forceinline__ uint32_t threefry32(uint32_t k0, uint32_t k1,
                                               uint32_t x0, uint32_t x1) {
    uint32_t ks2 = k0 ^ k1 ^ 0x1BD11BDAu;
    x0 += k0; x1 += k1;
#define TFR(r) { x0 += x1; x1 = rotl32(x1, r); x1 ^= x0; }
    TFR(13) TFR(15) TFR(26) TFR(6)   x0 += k1;  x1 += ks2 + 1u;
    TFR(17) TFR(29) TFR(16) TFR(24)  x0 += ks2; x1 += k0 + 2u;
    TFR(13) TFR(15) TFR(26) TFR(6)   x0 += k0;  x1 += k1 + 3u;
    TFR(17) TFR(29) TFR(16) TFR(24)  x0 += k1;  x1 += ks2 + 4u;
    TFR(13) TFR(15) TFR(26) TFR(6)   x0 += ks2; x1 += k0 + 5u;
#undef TFR
    return x0 ^ x1;
}
__device__ __forceinline__ float jax_normal_from_bits(uint32_t bits) {
    float f = __uint_as_float((bits >> 9) | 0x3F800000u) - 1.0f;
    const float lo = -0.99999994f;
    float u = fmaf(f, 1.0f - lo, lo);
    u = fmaxf(lo, u);
    return 1.41421356f * erfinvf(u);
}

// ---------------- fused multi-value block reductions (128 threads) ----------
__device__ __forceinline__ void block_sum2(float& a, float& b, float* sR) {
#pragma unroll
    for (int o = 16; o; o >>= 1) {
        a += __shfl_xor_sync(0xffffffffu, a, o);
        b += __shfl_xor_sync(0xffffffffu, b, o);
    }
    int warp = threadIdx.x >> 5;
    __syncthreads();
    if ((threadIdx.x & 31) == 0) { sR[warp] = a; sR[4 + warp] = b; }
    __syncthreads();
    a = (sR[0] + sR[1]) + (sR[2] + sR[3]);
    b = (sR[4] + sR[5]) + (sR[6] + sR[7]);
}
__device__ __forceinline__ void block_sum3(float& a, float& b, float& c, float* sR) {
#pragma unroll
    for (int o = 16; o; o >>= 1) {
        a += __shfl_xor_sync(0xffffffffu, a, o);
        b += __shfl_xor_sync(0xffffffffu, b, o);
        c += __shfl_xor_sync(0xffffffffu, c, o);
    }
    int warp = threadIdx.x >> 5;
    __syncthreads();
    if ((threadIdx.x & 31) == 0) { sR[warp] = a; sR[4 + warp] = b; sR[8 + warp] = c; }
    __syncthreads();
    a = (sR[0] + sR[1]) + (sR[2] + sR[3]);
    b = (sR[4] + sR[5]) + (sR[6] + sR[7]);
    c = (sR[8] + sR[9]) + (sR[10] + sR[11]);
}
__device__ __forceinline__ void block_sum4(float& a, float& b, float& c, float& d,
                                           float* sR) {
#pragma unroll
    for (int o = 16; o; o >>= 1) {
        a += __shfl_xor_sync(0xffffffffu, a, o);
        b += __shfl_xor_sync(0xffffffffu, b, o);
        c += __shfl_xor_sync(0xffffffffu, c, o);
        d += __shfl_xor_sync(0xffffffffu, d, o);
    }
    int warp = threadIdx.x >> 5;
    __syncthreads();
    if ((threadIdx.x & 31) == 0) {
        sR[warp] = a; sR[4 + warp] = b; sR[8 + warp] = c; sR[12 + warp] = d;
    }
    __syncthreads();
    a = (sR[0]  + sR[1])  + (sR[2]  + sR[3]);
    b = (sR[4]  + sR[5])  + (sR[6]  + sR[7]);
    c = (sR[8]  + sR[9])  + (sR[10] + sR[11]);
    d = (sR[12] + sR[13]) + (sR[14] + sR[15]);
}
__device__ __forceinline__ float block_sum1(float v, float* sR) {
#pragma unroll
    for (int o = 16; o; o >>= 1) v += __shfl_xor_sync(0xffffffffu, v, o);
    __syncthreads();
    if ((threadIdx.x & 31) == 0) sR[threadIdx.x >> 5] = v;
    __syncthreads();
    return (sR[0] + sR[1]) + (sR[2] + sR[3]);
}

// ---------------- kernel 2: fused BAM + epilogue + last-block KL ------------
__global__ __launch_bounds__(128) void main_kernel(
    const float* __restrict__ user_emb, const float* __restrict__ item_emb,
    const float* __restrict__ v_att,
    const float* __restrict__ ln_u_g,   const float* __restrict__ ln_u_b,
    const float* __restrict__ ln_i_g,   const float* __restrict__ ln_i_b,
    const float* __restrict__ pred_W,   const float* __restrict__ pred_b,
    const int*   __restrict__ user_hist,const int*  __restrict__ user_idx,
    const int*   __restrict__ item_idx, float* __restrict__ out, int pad_id,
    int B, int out_idx)
{
    __shared__ float sQ[DD];
    __shared__ int   sOffH[LL], sMask[LL];     // bf16-table byte offset r*256
    __shared__ float sS[LL], sW1[LL], sW2[LL]; // sS holds exp(s) (0 if masked)
    __shared__ float sRed[16];
    __shared__ int   sLast;

    int b = blockIdx.x, tid = threadIdx.x;
    int u = user_idx[b], t = item_idx[b];

    float cnt_t = 0.f;
    for (int l = tid; l < LL; l += 128) {
        int r = user_hist[(size_t)u * LL + l];
        sOffH[l] = r << 8;                     // r * 128 * 2 bytes (bf16)
        int mk = (r != t) && (r != pad_id);
        sMask[l] = mk;
        cnt_t += (float)mk;
    }
    sQ[tid] = user_emb[(size_t)u * DD + tid];
    __syncthreads();

    int lane = tid & 31, warp = tid >> 5;

    // ---- scores+exp fused, branch-free: warp = 2 l/iter, 16 lanes x 8 dims.
    // No max-subtraction: |s| <= |v|_1/4 (tanh bounded) so exp is safe.
    float esum_t = 0.f;
    {
        int half = lane >> 4, hl = lane & 15;
        int d0 = hl * 8;
        const float* qp = &g_qWb[(size_t)b * DD + d0];
        float4 qa = *reinterpret_cast<const float4*>(qp);
        float4 qb = *reinterpret_cast<const float4*>(qp + 4);
        float4 va = __ldg(reinterpret_cast<const float4*>(&v_att[d0]));
        float4 vb = __ldg(reinterpret_cast<const float4*>(&v_att[d0 + 4]));
        const char* kb = reinterpret_cast<const char*>(g_kWh) + d0 * 2;
        int lbase = warp * 2 + half;
#pragma unroll 5
        for (int i = 0; i < 25; ++i) {
            int l = lbase + i * 8;
            uint4 kv = __ldg(reinterpret_cast<const uint4*>(
                kb + (uint32_t)sOffH[l]));
            float2 f0 = __bfloat1622float2(*reinterpret_cast<__nv_bfloat162*>(&kv.x));
            float2 f1 = __bfloat1622float2(*reinterpret_cast<__nv_bfloat162*>(&kv.y));
            float2 f2 = __bfloat1622float2(*reinterpret_cast<__nv_bfloat162*>(&kv.z));
            float2 f3 = __bfloat1622float2(*reinterpret_cast<__nv_bfloat162*>(&kv.w));
            float p =      tanh_hw(qa.x + f0.x) * va.x;
            p = fmaf(tanh_hw(qa.y + f0.y), va.y, p);
            p = fmaf(tanh_hw(qa.z + f1.x), va.z, p);
            p = fmaf(tanh_hw(qa.w + f1.y), va.w, p);
            p = fmaf(tanh_hw(qb.x + f2.x), vb.x, p);
            p = fmaf(tanh_hw(qb.y + f2.y), vb.y, p);
            p = fmaf(tanh_hw(qb.z + f3.x), vb.z, p);
            p = fmaf(tanh_hw(qb.w + f3.y), vb.w, p);
#pragma unroll
            for (int o = 8; o; o >>= 1) p += __shfl_xor_sync(0xffffffffu, p, o);
            float e = __expf(p * 0.25f);
            e = sMask[l] ? e : 0.f;
            if (hl == 0) { sS[l] = e; esum_t += e; }
        }
    }
    float esum = esum_t, cnt = cnt_t;
    block_sum2(esum, cnt, sRed);
    float nv   = fmaxf(cnt, 1.f);
    float mu_p = -__logf(nv);
    float invE = 1.f / esum;

    // ---- sampled weights (two draws, shared alpha) + KL, branch-free ----
    float klacc = 0.f, ws1 = 0.f, ws2 = 0.f;
    uint32_t b200 = (uint32_t)b * LL;
    for (int l = tid; l < LL; l += 128) {
        int   mk = sMask[l];
        float a  = fmaf(sS[l], invE, 1e-24f);
        float mu = __logf(a);
        float dd = mu - mu_p;
        klacc += mk ? (1.8075851f + dd * dd * 0.5f) : 0.f;
        uint32_t idx = b200 + (uint32_t)l;
        float e1 = jax_normal_from_bits(threefry32(0u, 1u, 0u, idx));
        float e2 = jax_normal_from_bits(threefry32(0u, 2u, 0u, idx));
        float w1 = mk ? a * __expf(0.1f * e1) : 0.f;
        float w2 = mk ? a * __expf(0.1f * e2) : 0.f;
        sW1[l] = w1; sW2[l] = w2; ws1 += w1; ws2 += w2;
    }
    block_sum3(klacc, ws1, ws2, sRed);
    if (tid == 0) { g_klsum[b] = klacc; g_nvalid[b] = cnt; }
    float i1 = 1.f / (ws1 + 1e-12f), i2 = 1.f / (ws2 + 1e-12f);

    // ---- ctx accumulation: thread = dim, deep-unrolled gathers ----
    float a1 = 0.f, a2 = 0.f;
    const char* ieb = reinterpret_cast<const char*>(item_emb) + tid * 4;
#pragma unroll 4
    for (int l4 = 0; l4 < LL / 4; ++l4) {
        float4 w1 = *reinterpret_cast<const float4*>(&sW1[l4 * 4]);
        float4 w2 = *reinterpret_cast<const float4*>(&sW2[l4 * 4]);
        int4   rr = *reinterpret_cast<const int4*>(&sOffH[l4 * 4]);
        float v0 = __ldg(reinterpret_cast<const float*>(ieb + 2 * (size_t)(uint32_t)rr.x));
        float v1 = __ldg(reinterpret_cast<const float*>(ieb + 2 * (size_t)(uint32_t)rr.y));
        float v2 = __ldg(reinterpret_cast<const float*>(ieb + 2 * (size_t)(uint32_t)rr.z));
        float v3 = __ldg(reinterpret_cast<const float*>(ieb + 2 * (size_t)(uint32_t)rr.w));
        a1 = fmaf(w1.x, v0, a1); a2 = fmaf(w2.x, v0, a2);
        a1 = fmaf(w1.y, v1, a1); a2 = fmaf(w2.y, v1, a2);
        a1 = fmaf(w1.z, v2, a1); a2 = fmaf(w2.z, v2, a2);
        a1 = fmaf(w1.w, v3, a1); a2 = fmaf(w2.w, v3, a2);
    }
    a1 *= i1; a2 *= i2;

    // ---- epilogue: 2x single-pass layernorm + GMF fuse + head ----
    float pu = a1 * sQ[tid];
    float pi = a2 * __ldg(&item_emb[(size_t)t * DD + tid]);
    float su = pu, squ = pu * pu, si = pi, sqi = pi * pi;
    block_sum4(su, squ, si, sqi, sRed);
    float mu_  = su * (1.f / DD);
    float var  = squ * (1.f / DD) - mu_ * mu_;
    float mi_  = si * (1.f / DD);
    float var2 = sqi * (1.f / DD) - mi_ * mi_;
    float us = fmaf((pu - mu_) * rsqrtf(var + 1e-5f),  ln_u_g[tid], ln_u_b[tid]);
    float is = fmaf((pi - mi_) * rsqrtf(var2 + 1e-5f), ln_i_g[tid], ln_i_b[tid]);

    float tot = block_sum1(us * is * pred_W[tid], sRed);
    if (tid == 0) out[b] = tot + pred_b[0];

    // ---- last-block deterministic KL finalize ----
    if (out_idx >= 0) {
        if (tid == 0) {
            __threadfence();
            sLast = (atomicAdd(&g_ctr, 1) == B - 1);
        }
        __syncthreads();
        if (sLast) {
            __threadfence();
            float k = 0.f, n = 0.f;
            for (int i = tid; i < B; i += 128) { k += g_klsum[i]; n += g_nvalid[i]; }
            block_sum2(k, n, sRed);
            if (tid == 0) {
                out[out_idx] = 0.25f * k / fmaxf(n, 1.f);
                g_ctr = 0;
            }
        }
    }
}

// ---------------- launch ----------------------------------------------------
extern "C" void kernel_launch(void* const* d_in, const int* in_sizes, int n_in,
                              void* d_out, int out_size)
{
    const float* user_emb = (const float*)d_in[0];
    const float* item_emb = (const float*)d_in[1];
    const float* Wq       = (const float*)d_in[2];
    const float* Wk       = (const float*)d_in[3];
    const float* b_att    = (const float*)d_in[4];
    const float* v_att    = (const float*)d_in[5];
    const float* ln_u_g   = (const float*)d_in[6];
    const float* ln_u_b   = (const float*)d_in[7];
    const float* ln_i_g   = (const float*)d_in[8];
    const float* ln_i_b   = (const float*)d_in[9];
    const float* pred_W   = (const float*)d_in[10];
    const float* pred_b   = (const float*)d_in[11];
    const int*   user_hist= (const int*)d_in[12];
    const int*   user_idx = (const int*)d_in[13];
    const int*   item_idx = (const int*)d_in[14];

    int B      = in_sizes[13];
    int n_rows = in_sizes[1] / DD;      // 100001
    int pad_id = n_rows - 1;
    int out_idx = (out_size > B) ? (out_size - 1) : -1;
    int kwBlocks = (n_rows + 127) / 128;
    int qwBlocks = (B + 127) / 128;

    cudaFuncSetAttribute(gemm_kernel,
                         cudaFuncAttributeMaxDynamicSharedMemorySize,
                         GEMM_SMEM_BYTES);

    wkt_kernel<<<32, 256>>>(Wk, Wq);
    gemm_kernel<<<kwBlocks + qwBlocks, 256, GEMM_SMEM_BYTES>>>(
        item_emb, user_emb, b_att, user_idx, n_rows, B, kwBlocks);
    main_kernel<<<B, 128>>>(user_emb, item_emb, v_att,
                            ln_u_g, ln_u_b, ln_i_g, ln_i_b, pred_W, pred_b,
                            user_hist, user_idx, item_idx, (float*)d_out, pad_id,
                            B, out_idx);
}

// round 12
// speedup vs baseline: 2.7143x; 1.1091x over previous
#include <cuda_runtime.h>
#include <cuda_bf16.h>
#include <stdint.h>

#define DD 128
#define LL 200

// ---------------- device scratch (static globals: allocation-free) ----------
__device__ __nv_bfloat16 g_kWh[(size_t)100001 * DD];  // (item_emb @ Wk) in bf16
__device__ __nv_bfloat16 g_WkT[DD * DD];              // Wk^T, bf16
__device__ __nv_bfloat16 g_WqT[DD * DD];              // Wq^T, bf16
__device__ float g_qWb[(size_t)8192 * DD];            // user_emb[uidx]@Wq + b_att
__device__ float g_klsum[8192];
__device__ float g_nvalid[8192];
__device__ int   g_ctr;                               // self-resetting counter

__device__ __forceinline__ float tanh_hw(float x) {
    float t; asm("tanh.approx.f32 %0, %1;" : "=f"(t) : "f"(x)); return t;
}

// ---------------- kernel 0: transpose Wk, Wq -> bf16 ------------------------
__global__ __launch_bounds__(256) void wkt_kernel(
    const float* __restrict__ Wk, const float* __restrict__ Wq)
{
    __shared__ float tile[32][33];
    int which = blockIdx.x >> 4;
    int bi = blockIdx.x & 15;
    const float* src = which ? Wq : Wk;
    __nv_bfloat16* dst = which ? g_WqT : g_WkT;
    int bx = (bi & 3) * 32;             // n tile
    int by = (bi >> 2) * 32;            // k tile
    int tx = threadIdx.x & 31, ty = threadIdx.x >> 5;
#pragma unroll
    for (int j = 0; j < 4; ++j)
        tile[ty + j * 8][tx] = src[(by + ty + j * 8) * DD + bx + tx];
    __syncthreads();
#pragma unroll
    for (int j = 0; j < 4; ++j)
        dst[(bx + ty + j * 8) * DD + by + tx] =
            __float2bfloat16(tile[tx][ty + j * 8]);
}

// ---------------- bf16 mma tile: C[128x128] = A @ W^T -----------------------
#define TSH 136
#define GEMM_SMEM_BYTES (2 * 128 * TSH * 2)

template <bool GATHER, bool OUT_BF16>
__device__ __forceinline__ void mma_bf16_tile(
    const float* __restrict__ Arows, const int* __restrict__ gidx,
    const __nv_bfloat16* __restrict__ WT, const float* __restrict__ bias,
    void* __restrict__ Cout, size_t base, int n_rows, __nv_bfloat16* sh)
{
    __nv_bfloat16* As = sh;                 // [128][TSH]
    __nv_bfloat16* Bs = sh + 128 * TSH;     // [128][TSH] (n-major)
    int tid = threadIdx.x, lane = tid & 31, warp = tid >> 5;

    const float4* A4 = reinterpret_cast<const float4*>(Arows);
#pragma unroll
    for (int j = 0; j < 16; ++j) {
        int f = tid + j * 256;              // 0..4095
        int m = f >> 5, kc = f & 31;
        size_t gi = base + m; if (gi >= (size_t)n_rows) gi = n_rows - 1;
        if (GATHER) gi = (size_t)gidx[gi];
        float4 v = A4[gi * 32 + kc];
        __nv_bfloat162 lo = __floats2bfloat162_rn(v.x, v.y);
        __nv_bfloat162 hi = __floats2bfloat162_rn(v.z, v.w);
        *reinterpret_cast<uint2*>(&As[m * TSH + kc * 4]) =
            make_uint2(*reinterpret_cast<uint32_t*>(&lo),
                       *reinterpret_cast<uint32_t*>(&hi));
    }
    const uint4* W4 = reinterpret_cast<const uint4*>(WT);
#pragma unroll
    for (int j = 0; j < 8; ++j) {
        int f = tid + j * 256;              // 0..2047
        int n = f >> 4, kc = f & 15;
        *reinterpret_cast<uint4*>(&Bs[n * TSH + kc * 8]) = W4[f];
    }
    __syncthreads();

    int gq = lane >> 2, tg2 = (lane & 3) * 2;
    int mrow = (warp >> 1) * 32;
    int ncol = (warp & 1) * 64;

    float c[2][8][4];
#pragma unroll
    for (int mi = 0; mi < 2; ++mi)
#pragma unroll
        for (int nt = 0; nt < 8; ++nt)
#pragma unroll
            for (int i = 0; i < 4; ++i) c[mi][nt][i] = 0.f;

#pragma unroll
    for (int ks = 0; ks < 8; ++ks) {
        int k0 = ks * 16;
        uint32_t bq[8][2];
#pragma unroll
        for (int nt = 0; nt < 8; ++nt) {
            const __nv_bfloat16* bp = &Bs[(ncol + nt * 8 + gq) * TSH + k0 + tg2];
            bq[nt][0] = *reinterpret_cast<const uint32_t*>(bp);
            bq[nt][1] = *reinterpret_cast<const uint32_t*>(bp + 8);
        }
#pragma unroll
        for (int mi = 0; mi < 2; ++mi) {
            const __nv_bfloat16* ap0 = &As[(mrow + mi * 16 + gq) * TSH + k0 + tg2];
            const __nv_bfloat16* ap1 = ap0 + 8 * TSH;
            uint32_t a0 = *reinterpret_cast<const uint32_t*>(ap0);
            uint32_t a1 = *reinterpret_cast<const uint32_t*>(ap1);
            uint32_t a2 = *reinterpret_cast<const uint32_t*>(ap0 + 8);
            uint32_t a3 = *reinterpret_cast<const uint32_t*>(ap1 + 8);
#pragma unroll
            for (int nt = 0; nt < 8; ++nt) {
                asm volatile(
                    "mma.sync.aligned.m16n8k16.row.col.f32.bf16.bf16.f32 "
                    "{%0,%1,%2,%3}, {%4,%5,%6,%7}, {%8,%9}, {%0,%1,%2,%3};"
                    : "+f"(c[mi][nt][0]), "+f"(c[mi][nt][1]),
                      "+f"(c[mi][nt][2]), "+f"(c[mi][nt][3])
                    : "r"(a0), "r"(a1), "r"(a2), "r"(a3),
                      "r"(bq[nt][0]), "r"(bq[nt][1]));
            }
        }
    }

#pragma unroll
    for (int mi = 0; mi < 2; ++mi) {
        size_t g0 = base + mrow + mi * 16 + gq;
        bool ok0 = g0 < (size_t)n_rows, ok1 = (g0 + 8) < (size_t)n_rows;
#pragma unroll
        for (int nt = 0; nt < 8; ++nt) {
            int col = ncol + nt * 8 + tg2;
            if (OUT_BF16) {
                __nv_bfloat16* Ch = reinterpret_cast<__nv_bfloat16*>(Cout);
                if (ok0) *reinterpret_cast<__nv_bfloat162*>(&Ch[g0 * DD + col])
                             = __floats2bfloat162_rn(c[mi][nt][0], c[mi][nt][1]);
                if (ok1) *reinterpret_cast<__nv_bfloat162*>(&Ch[(g0 + 8) * DD + col])
                             = __floats2bfloat162_rn(c[mi][nt][2], c[mi][nt][3]);
            } else {
                float* Cf = reinterpret_cast<float*>(Cout);
                float bx = __ldg(&bias[col]);
                float by = __ldg(&bias[col + 1]);
                if (ok0) *reinterpret_cast<float2*>(&Cf[g0 * DD + col])
                             = make_float2(c[mi][nt][0] + bx, c[mi][nt][1] + by);
                if (ok1) *reinterpret_cast<float2*>(&Cf[(g0 + 8) * DD + col])
                             = make_float2(c[mi][nt][2] + bx, c[mi][nt][3] + by);
            }
        }
    }
}

// ---------------- kernel 1: merged kW + qW GEMMs ----------------------------
__global__ __launch_bounds__(256, 2) void gemm_kernel(
    const float* __restrict__ item_emb, const float* __restrict__ user_emb,
    const float* __restrict__ b_att, const int* __restrict__ user_idx,
    int n_rows, int B, int kwBlocks)
{
    extern __shared__ __nv_bfloat16 sh[];
    if ((int)blockIdx.x < kwBlocks) {
        mma_bf16_tile<false, true>(item_emb, nullptr, g_WkT, nullptr, g_kWh,
                                   (size_t)blockIdx.x * 128, n_rows, sh);
    } else {
        mma_bf16_tile<true, false>(user_emb, user_idx, g_WqT, b_att, g_qWb,
                                   (size_t)(blockIdx.x - kwBlocks) * 128, B, sh);
    }
}

// ---------------- threefry2x32 (JAX-compatible) -----------------------------
__device__ __forceinline__ uint32_t rotl32(uint32_t x, int r) {
    return (x << r) | (x >> (32 - r));
}
__device__ __forceinline__ uint32_t threefry32(uint32_t k0, uint32_t k1,
                                               uint32_t x0, uint32_t x1) {
    uint32_t ks2 = k0 ^ k1 ^ 0x1BD11BDAu;
    x0 += k0; x1 += k1;
#define TFR(r) { x0 += x1; x1 = rotl32(x1, r); x1 ^= x0; }
    TFR(13) TFR(15) TFR(26) TFR(6)   x0 += k1;  x1 += ks2 + 1u;
    TFR(17) TFR(29) TFR(16) TFR(24)  x0 += ks2; x1 += k0 + 2u;
    TFR(13) TFR(15) TFR(26) TFR(6)   x0 += k0;  x1 += k1 + 3u;
    TFR(17) TFR(29) TFR(16) TFR(24)  x0 += k1;  x1 += ks2 + 4u;
    TFR(13) TFR(15) TFR(26) TFR(6)   x0 += ks2; x1 += k0 + 5u;
#undef TFR
    return x0 ^ x1;
}
__device__ __forceinline__ float jax_normal_from_bits(uint32_t bits) {
    float f = __uint_as_float((bits >> 9) | 0x3F800000u) - 1.0f;
    const float lo = -0.99999994f;
    float u = fmaf(f, 1.0f - lo, lo);
    u = fmaxf(lo, u);
    return 1.41421356f * erfinvf(u);
}

// ---------------- fused multi-value block reductions (128 threads) ----------
__device__ __forceinline__ void block_sum2(float& a, float& b, float* sR) {
#pragma unroll
    for (int o = 16; o; o >>= 1) {
        a += __shfl_xor_sync(0xffffffffu, a, o);
        b += __shfl_xor_sync(0xffffffffu, b, o);
    }
    int warp = threadIdx.x >> 5;
    __syncthreads();
    if ((threadIdx.x & 31) == 0) { sR[warp] = a; sR[4 + warp] = b; }
    __syncthreads();
    a = (sR[0] + sR[1]) + (sR[2] + sR[3]);
    b = (sR[4] + sR[5]) + (sR[6] + sR[7]);
}
__device__ __forceinline__ void block_sum3(float& a, float& b, float& c, float* sR) {
#pragma unroll
    for (int o = 16; o; o >>= 1) {
        a += __shfl_xor_sync(0xffffffffu, a, o);
        b += __shfl_xor_sync(0xffffffffu, b, o);
        c += __shfl_xor_sync(0xffffffffu, c, o);
    }
    int warp = threadIdx.x >> 5;
    __syncthreads();
    if ((threadIdx.x & 31) == 0) { sR[warp] = a; sR[4 + warp] = b; sR[8 + warp] = c; }
    __syncthreads();
    a = (sR[0] + sR[1]) + (sR[2] + sR[3]);
    b = (sR[4] + sR[5]) + (sR[6] + sR[7]);
    c = (sR[8] + sR[9]) + (sR[10] + sR[11]);
}
__device__ __forceinline__ void block_sum4(float& a, float& b, float& c, float& d,
                                           float* sR) {
#pragma unroll
    for (int o = 16; o; o >>= 1) {
        a += __shfl_xor_sync(0xffffffffu, a, o);
        b += __shfl_xor_sync(0xffffffffu, b, o);
        c += __shfl_xor_sync(0xffffffffu, c, o);
        d += __shfl_xor_sync(0xffffffffu, d, o);
    }
    int warp = threadIdx.x >> 5;
    __syncthreads();
    if ((threadIdx.x & 31) == 0) {
        sR[warp] = a; sR[4 + warp] = b; sR[8 + warp] = c; sR[12 + warp] = d;
    }
    __syncthreads();
    a = (sR[0]  + sR[1])  + (sR[2]  + sR[3]);
    b = (sR[4]  + sR[5])  + (sR[6]  + sR[7]);
    c = (sR[8]  + sR[9])  + (sR[10] + sR[11]);
    d = (sR[12] + sR[13]) + (sR[14] + sR[15]);
}
__device__ __forceinline__ float block_sum1(float v, float* sR) {
#pragma unroll
    for (int o = 16; o; o >>= 1) v += __shfl_xor_sync(0xffffffffu, v, o);
    __syncthreads();
    if ((threadIdx.x & 31) == 0) sR[threadIdx.x >> 5] = v;
    __syncthreads();
    return (sR[0] + sR[1]) + (sR[2] + sR[3]);
}

// ---------------- kernel 2: fused BAM + epilogue + last-block KL ------------
// __launch_bounds__(128, 16): cap at 32 regs -> 16 CTAs/SM (occupancy push;
// any spills land in the cold threefry/epilogue regions, off the gather path).
__global__ __launch_bounds__(128, 16) void main_kernel(
    const float* __restrict__ user_emb, const float* __restrict__ item_emb,
    const float* __restrict__ v_att,
    const float* __restrict__ ln_u_g,   const float* __restrict__ ln_u_b,
    const float* __restrict__ ln_i_g,   const float* __restrict__ ln_i_b,
    const float* __restrict__ pred_W,   const float* __restrict__ pred_b,
    const int*   __restrict__ user_hist,const int*  __restrict__ user_idx,
    const int*   __restrict__ item_idx, float* __restrict__ out, int pad_id,
    int B, int out_idx)
{
    __shared__ float sQ[DD];
    __shared__ int   sOffH[LL], sMask[LL];     // bf16-table byte offset r*256
    __shared__ float sS[LL], sW1[LL], sW2[LL]; // sS holds exp(s) (0 if masked)
    __shared__ float sRed[16];
    __shared__ int   sLast;

    int b = blockIdx.x, tid = threadIdx.x;
    int u = user_idx[b], t = item_idx[b];

    float cnt_t = 0.f;
    for (int l = tid; l < LL; l += 128) {
        int r = user_hist[(size_t)u * LL + l];
        sOffH[l] = r << 8;                     // r * 128 * 2 bytes (bf16)
        int mk = (r != t) && (r != pad_id);
        sMask[l] = mk;
        cnt_t += (float)mk;
    }
    sQ[tid] = user_emb[(size_t)u * DD + tid];
    __syncthreads();

    int lane = tid & 31, warp = tid >> 5;

    // ---- scores+exp fused, branch-free: warp = 2 l/iter, 16 lanes x 8 dims.
    // No max-subtraction: |s| <= |v|_1/4 (tanh bounded) so exp is safe.
    float esum_t = 0.f;
    {
        int half = lane >> 4, hl = lane & 15;
        int d0 = hl * 8;
        const float* qp = &g_qWb[(size_t)b * DD + d0];
        float4 qa = *reinterpret_cast<const float4*>(qp);
        float4 qb = *reinterpret_cast<const float4*>(qp + 4);
        float4 va = __ldg(reinterpret_cast<const float4*>(&v_att[d0]));
        float4 vb = __ldg(reinterpret_cast<const float4*>(&v_att[d0 + 4]));
        const char* kb = reinterpret_cast<const char*>(g_kWh) + d0 * 2;
        int lbase = warp * 2 + half;
#pragma unroll 5
        for (int i = 0; i < 25; ++i) {
            int l = lbase + i * 8;
            uint4 kv = __ldg(reinterpret_cast<const uint4*>(
                kb + (uint32_t)sOffH[l]));
            float2 f0 = __bfloat1622float2(*reinterpret_cast<__nv_bfloat162*>(&kv.x));
            float2 f1 = __bfloat1622float2(*reinterpret_cast<__nv_bfloat162*>(&kv.y));
            float2 f2 = __bfloat1622float2(*reinterpret_cast<__nv_bfloat162*>(&kv.z));
            float2 f3 = __bfloat1622float2(*reinterpret_cast<__nv_bfloat162*>(&kv.w));
            float p =      tanh_hw(qa.x + f0.x) * va.x;
            p = fmaf(tanh_hw(qa.y + f0.y), va.y, p);
            p = fmaf(tanh_hw(qa.z + f1.x), va.z, p);
            p = fmaf(tanh_hw(qa.w + f1.y), va.w, p);
            p = fmaf(tanh_hw(qb.x + f2.x), vb.x, p);
            p = fmaf(tanh_hw(qb.y + f2.y), vb.y, p);
            p = fmaf(tanh_hw(qb.z + f3.x), vb.z, p);
            p = fmaf(tanh_hw(qb.w + f3.y), vb.w, p);
#pragma unroll
            for (int o = 8; o; o >>= 1) p += __shfl_xor_sync(0xffffffffu, p, o);
            float e = __expf(p * 0.25f);
            e = sMask[l] ? e : 0.f;
            if (hl == 0) { sS[l] = e; esum_t += e; }
        }
    }
    float esum = esum_t, cnt = cnt_t;
    block_sum2(esum, cnt, sRed);
    float nv   = fmaxf(cnt, 1.f);
    float mu_p = -__logf(nv);
    float invE = 1.f / esum;

    // ---- sampled weights (two draws, shared alpha) + KL, branch-free ----
    float klacc = 0.f, ws1 = 0.f, ws2 = 0.f;
    uint32_t b200 = (uint32_t)b * LL;
    for (int l = tid; l < LL; l += 128) {
        int   mk = sMask[l];
        float a  = fmaf(sS[l], invE, 1e-24f);
        float mu = __logf(a);
        float dd = mu - mu_p;
        klacc += mk ? (1.8075851f + dd * dd * 0.5f) : 0.f;
        uint32_t idx = b200 + (uint32_t)l;
        float e1 = jax_normal_from_bits(threefry32(0u, 1u, 0u, idx));
        float e2 = jax_normal_from_bits(threefry32(0u, 2u, 0u, idx));
        float w1 = mk ? a * __expf(0.1f * e1) : 0.f;
        float w2 = mk ? a * __expf(0.1f * e2) : 0.f;
        sW1[l] = w1; sW2[l] = w2; ws1 += w1; ws2 += w2;
    }
    block_sum3(klacc, ws1, ws2, sRed);
    if (tid == 0) { g_klsum[b] = klacc; g_nvalid[b] = cnt; }
    float i1 = 1.f / (ws1 + 1e-12f), i2 = 1.f / (ws2 + 1e-12f);

    // ---- ctx accumulation: thread = dim, deep-unrolled gathers ----
    float a1 = 0.f, a2 = 0.f;
    const char* ieb = reinterpret_cast<const char*>(item_emb) + tid * 4;
#pragma unroll 4
    for (int l4 = 0; l4 < LL / 4; ++l4) {
        float4 w1 = *reinterpret_cast<const float4*>(&sW1[l4 * 4]);
        float4 w2 = *reinterpret_cast<const float4*>(&sW2[l4 * 4]);
        int4   rr = *reinterpret_cast<const int4*>(&sOffH[l4 * 4]);
        float v0 = __ldg(reinterpret_cast<const float*>(ieb + 2 * (size_t)(uint32_t)rr.x));
        float v1 = __ldg(reinterpret_cast<const float*>(ieb + 2 * (size_t)(uint32_t)rr.y));
        float v2 = __ldg(reinterpret_cast<const float*>(ieb + 2 * (size_t)(uint32_t)rr.z));
        float v3 = __ldg(reinterpret_cast<const float*>(ieb + 2 * (size_t)(uint32_t)rr.w));
        a1 = fmaf(w1.x, v0, a1); a2 = fmaf(w2.x, v0, a2);
        a1 = fmaf(w1.y, v1, a1); a2 = fmaf(w2.y, v1, a2);
        a1 = fmaf(w1.z, v2, a1); a2 = fmaf(w2.z, v2, a2);
        a1 = fmaf(w1.w, v3, a1); a2 = fmaf(w2.w, v3, a2);
    }
    a1 *= i1; a2 *= i2;

    // ---- epilogue: 2x single-pass layernorm + GMF fuse + head ----
    float pu = a1 * sQ[tid];
    float pi = a2 * __ldg(&item_emb[(size_t)t * DD + tid]);
    float su = pu, squ = pu * pu, si = pi, sqi = pi * pi;
    block_sum4(su, squ, si, sqi, sRed);
    float mu_  = su * (1.f / DD);
    float var  = squ * (1.f / DD) - mu_ * mu_;
    float mi_  = si * (1.f / DD);
    float var2 = sqi * (1.f / DD) - mi_ * mi_;
    float us = fmaf((pu - mu_) * rsqrtf(var + 1e-5f),  ln_u_g[tid], ln_u_b[tid]);
    float is = fmaf((pi - mi_) * rsqrtf(var2 + 1e-5f), ln_i_g[tid], ln_i_b[tid]);

    float tot = block_sum1(us * is * pred_W[tid], sRed);
    if (tid == 0) out[b] = tot + pred_b[0];

    // ---- last-block deterministic KL finalize ----
    if (out_idx >= 0) {
        if (tid == 0) {
            __threadfence();
            sLast = (atomicAdd(&g_ctr, 1) == B - 1);
        }
        __syncthreads();
        if (sLast) {
            __threadfence();
            float k = 0.f, n = 0.f;
            for (int i = tid; i < B; i += 128) { k += g_klsum[i]; n += g_nvalid[i]; }
            block_sum2(k, n, sRed);
            if (tid == 0) {
                out[out_idx] = 0.25f * k / fmaxf(n, 1.f);
                g_ctr = 0;
            }
        }
    }
}

// ---------------- launch ----------------------------------------------------
extern "C" void kernel_launch(void* const* d_in, const int* in_sizes, int n_in,
                              void* d_out, int out_size)
{
    const float* user_emb = (const float*)d_in[0];
    const float* item_emb = (const float*)d_in[1];
    const float* Wq       = (const float*)d_in[2];
    const float* Wk       = (const float*)d_in[3];
    const float* b_att    = (const float*)d_in[4];
    const float* v_att    = (const float*)d_in[5];
    const float* ln_u_g   = (const float*)d_in[6];
    const float* ln_u_b   = (const float*)d_in[7];
    const float* ln_i_g   = (const float*)d_in[8];
    const float* ln_i_b   = (const float*)d_in[9];
    const float* pred_W   = (const float*)d_in[10];
    const float* pred_b   = (const float*)d_in[11];
    const int*   user_hist= (const int*)d_in[12];
    const int*   user_idx = (const int*)d_in[13];
    const int*   item_idx = (const int*)d_in[14];

    int B      = in_sizes[13];
    int n_rows = in_sizes[1] / DD;      // 100001
    int pad_id = n_rows - 1;
    int out_idx = (out_size > B) ? (out_size - 1) : -1;
    int kwBlocks = (n_rows + 127) / 128;
    int qwBlocks = (B + 127) / 128;

    cudaFuncSetAttribute(gemm_kernel,
                         cudaFuncAttributeMaxDynamicSharedMemorySize,
                         GEMM_SMEM_BYTES);

    wkt_kernel<<<32, 256>>>(Wk, Wq);
    gemm_kernel<<<kwBlocks + qwBlocks, 256, GEMM_SMEM_BYTES>>>(
        item_emb, user_emb, b_att, user_idx, n_rows, B, kwBlocks);
    main_kernel<<<B, 128>>>(user_emb, item_emb, v_att,
                            ln_u_g, ln_u_b, ln_i_g, ln_i_b, pred_W, pred_b,
                            user_hist, user_idx, item_idx, (float*)d_out, pad_id,
                            B, out_idx);
}